// round 3
// baseline (speedup 1.0000x reference)
#include <cuda_runtime.h>
#include <math.h>

// ---------------------------------------------------------------------------
// JointMambaFusion: B=4, C=128, H=W=128, D_INNER=256, D_STATE=16, DT_RANK=8
// 4 scans: T = {8192, 4096, 8192, 4096}; 16 (scan,batch) sequences, compact
// token bases c_TB[ib], total TOKTOT = 98304 tokens.
// ---------------------------------------------------------------------------

#define TOKTOT 98304

__constant__ int c_TB[16] = {
    0,     8192,  16384, 24576,      // i=0 (T=8192)
    32768, 36864, 40960, 45056,      // i=1 (T=4096)
    49152, 57344, 65536, 73728,      // i=2 (T=8192)
    81920, 86016, 90112, 94208       // i=3 (T=4096)
};

// scratch (device globals; no runtime allocation allowed)  ~587 MB total
__device__ float g_XZ   [TOKTOT * 512];   // in_proj output: xl | z(silu'd by conv kernel)
__device__ float g_XS   [TOKTOT * 256];   // post conv+silu  (u)
__device__ float g_XDBL [TOKTOT * 40];    // dt(8) | B(16) | C(16)
__device__ float g_DELTA[TOKTOT * 256];
__device__ float g_YT   [TOKTOT * 256];   // scan output, d-major per sequence
__device__ float g_OUT  [TOKTOT * 128];   // out_proj output, token-major
__device__ float g_AB   [2 * 4 * 128 * 64 * 64];
__device__ float g_WTin [4 * 128 * 512];  // in_proj_w transposed  [c][e]
__device__ float g_WTxp [4 * 256 * 64];   // x_proj_w transposed, zero-padded to 64 cols
__device__ float g_WTout[4 * 256 * 128];  // out_proj_w transposed [d][o]

__device__ __forceinline__ int scanT(int i) { return (i & 1) ? 4096 : 8192; }

__device__ __forceinline__ float siluf(float x) {
    return __fdividef(x, 1.0f + __expf(-x));
}

// scan-direction gather: x_i[b, t, c] from feat_a / feat_b
__device__ __forceinline__ float gather_x(int i, int b, int t, int c,
                                          const float* __restrict__ fa,
                                          const float* __restrict__ fb) {
    int l = (i & 1) ? (8191 - 2 * t) : t;
    int base = (b * 128 + c) * 128;
    if (i < 2) {
        int hh = l >> 7, ww = l & 127;
        if (ww < 64) return fa[(base + 2 * hh) * 128 + 2 * ww];
        else         return fb[(base + 2 * hh) * 128 + 2 * ww - 128];
    } else {
        int ww = l >> 7, rr = l & 127;
        if (rr < 64) return fa[(base + 2 * rr) * 128 + 2 * ww];
        else         return fb[(base + 2 * rr - 128) * 128 + 2 * ww];
    }
}

// ---------------------------------------------------------------------------
// K0: transpose weights into GEMM-friendly K-major layouts
// ---------------------------------------------------------------------------
__global__ void k_prep(const float* __restrict__ inw,
                       const float* __restrict__ xpw,
                       const float* __restrict__ outw) {
    int idx = blockIdx.x * 256 + threadIdx.x;
    if (idx < 4 * 512 * 128) {        // WTin[i][c][e] = inw[i][e][c]
        int i = idx / (512 * 128), r = idx % (512 * 128);
        int e = r / 128, c = r % 128;
        g_WTin[(i * 128 + c) * 512 + e] = inw[idx];
    }
    if (idx < 4 * 256 * 64) {         // WTxp[i][c][e] (e<40 valid, else 0)
        int i = idx / (256 * 64), r = idx % (256 * 64);
        int c = r / 64, e = r % 64;
        g_WTxp[idx] = (e < 40) ? xpw[(i * 40 + e) * 256 + c] : 0.0f;
    }
    if (idx < 4 * 256 * 128) {        // WTout[i][c][o] = outw[i][o][c]
        int i = idx / (256 * 128), r = idx % (256 * 128);
        int c = r / 128, o = r % 128;
        g_WTout[idx] = outw[(i * 128 + o) * 256 + c];
    }
}

// ---------------------------------------------------------------------------
// K1: in_proj GEMM (gather fused into A-tile load).  K=128, N=512.
// tile: 64 tokens x 64 cols, 256 threads, 4x4 micro-tile.
// ---------------------------------------------------------------------------
__global__ void k_gemm_in(const float* __restrict__ fa, const float* __restrict__ fb) {
    __shared__ float As[64][65];
    __shared__ float Ws[64][64];
    int nt = blockIdx.x;                 // 0..7  (col tile of 512)
    int tt = blockIdx.y;                 // token tile
    int ib = blockIdx.z;
    int i = ib >> 2, b = ib & 3;
    int T = scanT(i);
    if (tt * 64 >= T) return;
    int t0 = tt * 64;
    int tid = threadIdx.x;
    int tx = tid & 15, ty = tid >> 4;
    float acc[4][4] = {};
    for (int kc = 0; kc < 2; kc++) {
        for (int p = 0; p < 16; p++) {
            int idx = p * 256 + tid;
            int m = idx & 63, kk = idx >> 6;
            As[kk][m] = gather_x(i, b, t0 + m, kc * 64 + kk, fa, fb);
        }
        for (int p = 0; p < 16; p++) {
            int idx = p * 256 + tid;
            int n = idx & 63, kk = idx >> 6;
            Ws[kk][n] = g_WTin[(i * 128 + kc * 64 + kk) * 512 + nt * 64 + n];
        }
        __syncthreads();
#pragma unroll
        for (int kk = 0; kk < 64; kk++) {
            float4 bv = *(const float4*)&Ws[kk][tx * 4];
            float av[4];
#pragma unroll
            for (int im = 0; im < 4; im++) av[im] = As[kk][ty * 4 + im];
#pragma unroll
            for (int im = 0; im < 4; im++) {
                acc[im][0] = fmaf(av[im], bv.x, acc[im][0]);
                acc[im][1] = fmaf(av[im], bv.y, acc[im][1]);
                acc[im][2] = fmaf(av[im], bv.z, acc[im][2]);
                acc[im][3] = fmaf(av[im], bv.w, acc[im][3]);
            }
        }
        __syncthreads();
    }
    int SB = c_TB[ib];
#pragma unroll
    for (int im = 0; im < 4; im++) {
        int t = t0 + ty * 4 + im;
        float4 v = make_float4(acc[im][0], acc[im][1], acc[im][2], acc[im][3]);
        *(float4*)&g_XZ[(SB + t) * 512 + nt * 64 + tx * 4] = v;
    }
}

// ---------------------------------------------------------------------------
// K2: causal depthwise conv(4) + bias + silu on xl;  silu on z (in place)
// ---------------------------------------------------------------------------
__global__ void k_conv(const float* __restrict__ cw, const float* __restrict__ cb) {
    int t = blockIdx.x, ib = blockIdx.y;
    int i = ib >> 2;
    if (t >= scanT(i)) return;
    int d = threadIdx.x;
    int tok = c_TB[ib] + t;
    const float* row = &g_XZ[tok * 512];
    const float* w = &cw[(i * 256 + d) * 4];
    float acc = cb[i * 256 + d];
    if (t >= 3) acc = fmaf(row[-3 * 512 + d], w[0], acc);
    if (t >= 2) acc = fmaf(row[-2 * 512 + d], w[1], acc);
    if (t >= 1) acc = fmaf(row[-1 * 512 + d], w[2], acc);
    acc = fmaf(row[d], w[3], acc);
    g_XS[tok * 256 + d] = siluf(acc);
    float z = row[256 + d];
    g_XZ[tok * 512 + 256 + d] = siluf(z);
}

// ---------------------------------------------------------------------------
// K3: x_proj GEMM  (xs [T,256] @ WTxp [256,40->64])
// ---------------------------------------------------------------------------
__global__ void k_gemm_xp() {
    __shared__ float As[64][65];
    __shared__ float Ws[64][64];
    int tt = blockIdx.y;
    int ib = blockIdx.z;
    int i = ib >> 2;
    int T = scanT(i);
    if (tt * 64 >= T) return;
    int t0 = tt * 64;
    int SB = c_TB[ib];
    int tid = threadIdx.x;
    int tx = tid & 15, ty = tid >> 4;
    float acc[4][4] = {};
    for (int kc = 0; kc < 4; kc++) {
        for (int p = 0; p < 16; p++) {
            int idx = p * 256 + tid;
            int kk = idx & 63, m = idx >> 6;   // read k-fast (coalesced), write transposed
            As[kk][m] = g_XS[(SB + t0 + m) * 256 + kc * 64 + kk];
        }
        for (int p = 0; p < 16; p++) {
            int idx = p * 256 + tid;
            int n = idx & 63, kk = idx >> 6;
            Ws[kk][n] = g_WTxp[(i * 256 + kc * 64 + kk) * 64 + n];
        }
        __syncthreads();
#pragma unroll
        for (int kk = 0; kk < 64; kk++) {
            float4 bv = *(const float4*)&Ws[kk][tx * 4];
            float av[4];
#pragma unroll
            for (int im = 0; im < 4; im++) av[im] = As[kk][ty * 4 + im];
#pragma unroll
            for (int im = 0; im < 4; im++) {
                acc[im][0] = fmaf(av[im], bv.x, acc[im][0]);
                acc[im][1] = fmaf(av[im], bv.y, acc[im][1]);
                acc[im][2] = fmaf(av[im], bv.z, acc[im][2]);
                acc[im][3] = fmaf(av[im], bv.w, acc[im][3]);
            }
        }
        __syncthreads();
    }
    if (tx < 10) {   // only cols < 40 valid
#pragma unroll
        for (int im = 0; im < 4; im++) {
            int t = t0 + ty * 4 + im;
            float4 v = make_float4(acc[im][0], acc[im][1], acc[im][2], acc[im][3]);
            *(float4*)&g_XDBL[(SB + t) * 40 + tx * 4] = v;
        }
    }
}

// ---------------------------------------------------------------------------
// K4: dt_proj (K=8) + softplus -> delta
// ---------------------------------------------------------------------------
__global__ void k_delta(const float* __restrict__ dtw, const float* __restrict__ dtb) {
    int t = blockIdx.x, ib = blockIdx.y;
    int i = ib >> 2;
    if (t >= scanT(i)) return;
    int d = threadIdx.x;
    int tok = c_TB[ib] + t;
    const float* row = &g_XDBL[tok * 40];
    const float* wr = &dtw[(i * 256 + d) * 8];
    float pre = dtb[i * 256 + d];
#pragma unroll
    for (int r = 0; r < 8; r++) pre = fmaf(row[r], wr[r], pre);
    float sp = (pre > 20.0f) ? pre : log1pf(__expf(pre));
    g_DELTA[tok * 256 + d] = sp;
}

// ---------------------------------------------------------------------------
// K5: selective scan. thread = (ib, d, s); 16-lane butterfly over states.
// Output y (after +u*D and *silu(z)) stored d-major: g_YT[TB[ib]*256 + d*T + t].
// ---------------------------------------------------------------------------
__global__ void k_scan(const float* __restrict__ alog, const float* __restrict__ Dv) {
    int ib = blockIdx.y;
    int i = ib >> 2;
    int dg = blockIdx.x;                // 0..15
    int tid = threadIdx.x;
    int s = tid & 15, dl = tid >> 4;
    int d = dg * 16 + dl;
    int T = scanT(i);
    float Areg = -__expf(alog[(i * 256 + d) * 16 + s]);
    float Dreg = Dv[i * 256 + d];
    int base = c_TB[ib];
    const float* pD  = &g_DELTA[base * 256 + d];
    const float* pU  = &g_XS[base * 256 + d];
    const float* pBC = &g_XDBL[base * 40];
    const float* pZ  = &g_XZ[base * 512 + 256 + d];
    float* pY = &g_YT[base * 256 + d * T];
    float h = 0.0f;
    for (int tb = 0; tb < T; tb += 16) {
        float ybuf = 0.0f;
#pragma unroll
        for (int tt = 0; tt < 16; tt++) {
            int t = tb + tt;
            float dv = pD[t * 256];
            float u  = pU[t * 256];
            float Bv = pBC[t * 40 + 8 + s];
            float Cv = pBC[t * 40 + 24 + s];
            float e = __expf(dv * Areg);
            h = fmaf(e, h, (dv * u) * Bv);
            float p = h * Cv;
            p += __shfl_xor_sync(0xffffffffu, p, 1);
            p += __shfl_xor_sync(0xffffffffu, p, 2);
            p += __shfl_xor_sync(0xffffffffu, p, 4);
            p += __shfl_xor_sync(0xffffffffu, p, 8);
            float y = fmaf(u, Dreg, p) * pZ[t * 512];
            if (tt == s) ybuf = y;
        }
        pY[tb + s] = ybuf;   // 16 consecutive floats per half-warp
    }
}

// ---------------------------------------------------------------------------
// K6: out_proj GEMM  (yT [256][T] K-major  @  WTout [256][128])
// ---------------------------------------------------------------------------
__global__ void k_gemm_out() {
    __shared__ float As[64][65];
    __shared__ float Ws[64][64];
    int nt = blockIdx.x;                  // 0..1
    int tt = blockIdx.y;
    int ib = blockIdx.z;
    int i = ib >> 2;
    int T = scanT(i);
    if (tt * 64 >= T) return;
    int t0 = tt * 64;
    int SB = c_TB[ib];
    int tid = threadIdx.x;
    int tx = tid & 15, ty = tid >> 4;
    float acc[4][4] = {};
    for (int kc = 0; kc < 4; kc++) {
        for (int p = 0; p < 16; p++) {
            int idx = p * 256 + tid;
            int m = idx & 63, kk = idx >> 6;   // m(t) fast: coalesced, conflict-free
            As[kk][m] = g_YT[SB * 256 + (kc * 64 + kk) * T + t0 + m];
        }
        for (int p = 0; p < 16; p++) {
            int idx = p * 256 + tid;
            int n = idx & 63, kk = idx >> 6;
            Ws[kk][n] = g_WTout[(i * 256 + kc * 64 + kk) * 128 + nt * 64 + n];
        }
        __syncthreads();
#pragma unroll
        for (int kk = 0; kk < 64; kk++) {
            float4 bv = *(const float4*)&Ws[kk][tx * 4];
            float av[4];
#pragma unroll
            for (int im = 0; im < 4; im++) av[im] = As[kk][ty * 4 + im];
#pragma unroll
            for (int im = 0; im < 4; im++) {
                acc[im][0] = fmaf(av[im], bv.x, acc[im][0]);
                acc[im][1] = fmaf(av[im], bv.y, acc[im][1]);
                acc[im][2] = fmaf(av[im], bv.z, acc[im][2]);
                acc[im][3] = fmaf(av[im], bv.w, acc[im][3]);
            }
        }
        __syncthreads();
    }
#pragma unroll
    for (int im = 0; im < 4; im++) {
        int t = t0 + ty * 4 + im;
        float4 v = make_float4(acc[im][0], acc[im][1], acc[im][2], acc[im][3]);
        *(float4*)&g_OUT[(SB + t) * 128 + nt * 64 + tx * 4] = v;
    }
}

// interp of backward-scan output (len 4096 -> index 8191-l of the len-8192 signal)
__device__ __forceinline__ float interp_flip(int i, int b, int l, int c) {
    float pos = 0.5f * (float)(8191 - l) - 0.25f;
    pos = fminf(fmaxf(pos, 0.0f), 4095.0f);
    int lo = (int)floorf(pos);
    int hi = min(lo + 1, 4095);
    float w = pos - (float)lo;
    const float* ob = &g_OUT[c_TB[i * 4 + b] * 128 + c];
    return ob[lo * 128] * (1.0f - w) + ob[hi * 128] * w;
}

// ---------------------------------------------------------------------------
// K7: merge 4 scan outputs -> a,b maps [2][B][C][64][64] (smem transpose)
// ---------------------------------------------------------------------------
__global__ void k_merge() {
    __shared__ float S[64][129];
    int irow = blockIdx.x;               // 0..63
    int b = blockIdx.y;
    int tid = threadIdx.x;
    for (int half = 0; half < 2; half++) {
        for (int p = 0; p < 32; p++) {
            int idx = p * 256 + tid;
            int c = idx & 127, j = idx >> 7;
            int l  = irow * 128 + j + (half ? 64 : 0);
            int l2 = j * 128 + irow + (half ? 64 : 0);
            float v = g_OUT[(c_TB[b] + l) * 128 + c];
            v += interp_flip(1, b, l, c);
            v += g_OUT[(c_TB[8 + b] + l2) * 128 + c];
            v += interp_flip(3, b, l2, c);
            S[j][c] = v;
        }
        __syncthreads();
        for (int p = 0; p < 32; p++) {
            int idx = p * 256 + tid;
            int j = idx & 63, c = idx >> 6;
            g_AB[((half * 4 + b) * 128 + c) * 4096 + irow * 64 + j] = S[j][c];
        }
        __syncthreads();
    }
}

// ---------------------------------------------------------------------------
// K8: bilinear 64->128 upsample of a and b, + feat_a + feat_b
// ---------------------------------------------------------------------------
__global__ void k_final(const float* __restrict__ fa, const float* __restrict__ fb,
                        float* __restrict__ out) {
    int idx = blockIdx.x * 256 + threadIdx.x;
    int w = idx & 127, hh = (idx >> 7) & 127, c = (idx >> 14) & 127, b = idx >> 21;
    float ph = fminf(fmaxf(0.5f * hh - 0.25f, 0.0f), 63.0f);
    int h0 = (int)floorf(ph); int h1 = min(h0 + 1, 63); float wh = ph - (float)h0;
    float pw = fminf(fmaxf(0.5f * w - 0.25f, 0.0f), 63.0f);
    int w0 = (int)floorf(pw); int w1 = min(w0 + 1, 63); float ww = pw - (float)w0;
    const float* Aa = &g_AB[((0 * 4 + b) * 128 + c) * 4096];
    const float* Bb = &g_AB[((1 * 4 + b) * 128 + c) * 4096];
    float av = (Aa[h0 * 64 + w0] * (1.0f - ww) + Aa[h0 * 64 + w1] * ww) * (1.0f - wh)
             + (Aa[h1 * 64 + w0] * (1.0f - ww) + Aa[h1 * 64 + w1] * ww) * wh;
    float bv = (Bb[h0 * 64 + w0] * (1.0f - ww) + Bb[h0 * 64 + w1] * ww) * (1.0f - wh)
             + (Bb[h1 * 64 + w0] * (1.0f - ww) + Bb[h1 * 64 + w1] * ww) * wh;
    out[idx] = av + bv + fa[idx] + fb[idx];
}

// ---------------------------------------------------------------------------
extern "C" void kernel_launch(void* const* d_in, const int* in_sizes, int n_in,
                              void* d_out, int out_size) {
    (void)in_sizes; (void)n_in; (void)out_size;
    const float* fa   = (const float*)d_in[0];
    const float* fb   = (const float*)d_in[1];
    const float* inw  = (const float*)d_in[2];
    const float* cw   = (const float*)d_in[3];
    const float* cb   = (const float*)d_in[4];
    const float* xpw  = (const float*)d_in[5];
    const float* dtw  = (const float*)d_in[6];
    const float* dtb  = (const float*)d_in[7];
    const float* alog = (const float*)d_in[8];
    const float* Dv   = (const float*)d_in[9];
    const float* outw = (const float*)d_in[10];
    float* out = (float*)d_out;

    k_prep<<<1024, 256>>>(inw, xpw, outw);
    k_gemm_in<<<dim3(8, 128, 16), 256>>>(fa, fb);
    k_conv<<<dim3(8192, 16), 256>>>(cw, cb);
    k_gemm_xp<<<dim3(1, 128, 16), 256>>>();
    k_delta<<<dim3(8192, 16), 256>>>(dtw, dtb);
    k_scan<<<dim3(16, 16), 256>>>(alog, Dv);
    k_gemm_out<<<dim3(2, 128, 16), 256>>>();
    k_merge<<<dim3(64, 4), 256>>>();
    k_final<<<32768, 256>>>(fa, fb, out);
}

// round 5
// speedup vs baseline: 2.3000x; 2.3000x over previous
#include <cuda_runtime.h>
#include <math.h>

// ---------------------------------------------------------------------------
// JointMambaFusion: B=4, C=128, H=W=128, D_INNER=256, D_STATE=16, DT_RANK=8
// 4 scans: T = {8192, 4096, 8192, 4096}; 16 (scan,batch) sequences, compact
// token bases c_TB[ib], total TOKTOT = 98304 tokens.
// ---------------------------------------------------------------------------

#define TOKTOT 98304
#define NCHUNK 16

__constant__ int c_TB[16] = {
    0,     8192,  16384, 24576,      // i=0 (T=8192)
    32768, 36864, 40960, 45056,      // i=1 (T=4096)
    49152, 57344, 65536, 73728,      // i=2 (T=8192)
    81920, 86016, 90112, 94208       // i=3 (T=4096)
};

// scratch (device globals; no runtime allocation allowed)
__device__ float g_XZ   [TOKTOT * 512];   // in_proj output: xl | z (raw)
__device__ float g_XST  [TOKTOT * 256];   // post conv+silu (u), [d][t] per seq
__device__ float g_ZT   [TOKTOT * 256];   // silu(z), [d][t] per seq
__device__ float g_XDBL [TOKTOT * 40];    // dt(8) | B(16) | C(16), token-major
__device__ float g_DT   [TOKTOT * 256];   // delta, [d][t] per seq
__device__ float g_YT   [TOKTOT * 256];   // scan output, [d][t] per seq
__device__ float g_OUT  [TOKTOT * 128];   // out_proj output, token-major
__device__ float g_AB   [2 * 4 * 128 * 64 * 64];
__device__ float g_WTin [4 * 128 * 512];  // in_proj_w transposed  [c][e]
__device__ float g_WTxp [4 * 256 * 64];   // x_proj_w transposed, zero-padded
__device__ float g_WTout[4 * 256 * 128];  // out_proj_w transposed [d][o]
// chunked-scan state: [ib][chunk][d][s]
__device__ float g_CP [16 * NCHUNK * 256 * 16];
__device__ float g_CH [16 * NCHUNK * 256 * 16];
__device__ float g_HI [16 * NCHUNK * 256 * 16];
__device__ int   g_powBad;

__device__ __forceinline__ int scanT(int i) { return (i & 1) ? 4096 : 8192; }

__device__ __forceinline__ float siluf(float x) {
    return __fdividef(x, 1.0f + __expf(-x));
}

// scan-direction gather: x_i[b, t, c] from feat_a / feat_b
__device__ __forceinline__ float gather_x(int i, int b, int t, int c,
                                          const float* __restrict__ fa,
                                          const float* __restrict__ fb) {
    int l = (i & 1) ? (8191 - 2 * t) : t;
    int base = (b * 128 + c) * 128;
    if (i < 2) {
        int hh = l >> 7, ww = l & 127;
        if (ww < 64) return fa[(base + 2 * hh) * 128 + 2 * ww];
        else         return fb[(base + 2 * hh) * 128 + 2 * ww - 128];
    } else {
        int ww = l >> 7, rr = l & 127;
        if (rr < 64) return fa[(base + 2 * rr) * 128 + 2 * ww];
        else         return fb[(base + 2 * rr - 128) * 128 + 2 * ww];
    }
}

// ---------------------------------------------------------------------------
__global__ void k_reset() { g_powBad = 0; }

// K0: transpose weights + verify A_s = (s+1)*A_0 structure
__global__ void k_prep(const float* __restrict__ inw,
                       const float* __restrict__ xpw,
                       const float* __restrict__ outw,
                       const float* __restrict__ alog) {
    int idx = blockIdx.x * 256 + threadIdx.x;
    if (idx < 4 * 512 * 128) {        // WTin[i][c][e] = inw[i][e][c]
        int i = idx / (512 * 128), r = idx % (512 * 128);
        int e = r / 128, c = r % 128;
        g_WTin[(i * 128 + c) * 512 + e] = inw[idx];
    }
    if (idx < 4 * 256 * 64) {         // WTxp[i][c][e] (e<40 valid, else 0)
        int i = idx / (256 * 64), r = idx % (256 * 64);
        int c = r / 64, e = r % 64;
        g_WTxp[idx] = (e < 40) ? xpw[(i * 40 + e) * 256 + c] : 0.0f;
    }
    if (idx < 4 * 256 * 128) {        // WTout[i][c][o] = outw[i][o][c]
        int i = idx / (256 * 128), r = idx % (256 * 128);
        int c = r / 128, o = r % 128;
        g_WTout[idx] = outw[(i * 128 + o) * 256 + c];
    }
    if (idx < 4 * 256 * 16) {         // structure check
        int s = idx & 15;
        int dI = idx >> 4;            // i*256+d
        float As = -__expf(alog[dI * 16 + s]);
        float A0 = -__expf(alog[dI * 16]);
        float ratio = As / A0;
        if (fabsf(ratio - (float)(s + 1)) > 1e-5f * (float)(s + 1))
            atomicOr(&g_powBad, 1);
    }
}

// ---------------------------------------------------------------------------
// K1: in_proj GEMM (gather fused into A-tile load).  K=128, N=512.
// ---------------------------------------------------------------------------
__global__ void k_gemm_in(const float* __restrict__ fa, const float* __restrict__ fb) {
    __shared__ float As[64][65];
    __shared__ float Ws[64][64];
    int nt = blockIdx.x;
    int tt = blockIdx.y;
    int ib = blockIdx.z;
    int i = ib >> 2, b = ib & 3;
    int T = scanT(i);
    if (tt * 64 >= T) return;
    int t0 = tt * 64;
    int tid = threadIdx.x;
    int tx = tid & 15, ty = tid >> 4;
    float acc[4][4] = {};
    for (int kc = 0; kc < 2; kc++) {
        for (int p = 0; p < 16; p++) {
            int idx = p * 256 + tid;
            int m = idx & 63, kk = idx >> 6;
            As[kk][m] = gather_x(i, b, t0 + m, kc * 64 + kk, fa, fb);
        }
        for (int p = 0; p < 16; p++) {
            int idx = p * 256 + tid;
            int n = idx & 63, kk = idx >> 6;
            Ws[kk][n] = g_WTin[(i * 128 + kc * 64 + kk) * 512 + nt * 64 + n];
        }
        __syncthreads();
#pragma unroll
        for (int kk = 0; kk < 64; kk++) {
            float4 bv = *(const float4*)&Ws[kk][tx * 4];
            float av[4];
#pragma unroll
            for (int im = 0; im < 4; im++) av[im] = As[kk][ty * 4 + im];
#pragma unroll
            for (int im = 0; im < 4; im++) {
                acc[im][0] = fmaf(av[im], bv.x, acc[im][0]);
                acc[im][1] = fmaf(av[im], bv.y, acc[im][1]);
                acc[im][2] = fmaf(av[im], bv.z, acc[im][2]);
                acc[im][3] = fmaf(av[im], bv.w, acc[im][3]);
            }
        }
        __syncthreads();
    }
    int SB = c_TB[ib];
#pragma unroll
    for (int im = 0; im < 4; im++) {
        int t = t0 + ty * 4 + im;
        float4 v = make_float4(acc[im][0], acc[im][1], acc[im][2], acc[im][3]);
        *(float4*)&g_XZ[(SB + t) * 512 + nt * 64 + tx * 4] = v;
    }
}

// ---------------------------------------------------------------------------
// K2: conv+silu -> XST [d][t];  silu(z) -> ZT [d][t].  thread=d, 64-t chunk.
// ---------------------------------------------------------------------------
__global__ void k_conv(const float* __restrict__ cw, const float* __restrict__ cb) {
    int tc = blockIdx.x, ib = blockIdx.y;
    int i = ib >> 2;
    int T = scanT(i);
    if (tc * 64 >= T) return;
    int d = threadIdx.x;
    int SB = c_TB[ib];
    const float* w = &cw[(i * 256 + d) * 4];
    float w0 = w[0], w1 = w[1], w2 = w[2], w3 = w[3];
    float bias = cb[i * 256 + d];
    const float* px = &g_XZ[SB * 512 + d];
    float* pxs = &g_XST[SB * 256 + d * T];
    float* pzt = &g_ZT[SB * 256 + d * T];
    int t0 = tc * 64;
    float xm1 = (t0 >= 1) ? px[(t0 - 1) * 512] : 0.0f;
    float xm2 = (t0 >= 2) ? px[(t0 - 2) * 512] : 0.0f;
    float xm3 = (t0 >= 3) ? px[(t0 - 3) * 512] : 0.0f;
    for (int q4 = 0; q4 < 16; q4++) {
        float ob[4], zb[4];
#pragma unroll
        for (int j = 0; j < 4; j++) {
            int t = t0 + q4 * 4 + j;
            float x = px[t * 512];
            float acc = fmaf(x, w3, fmaf(xm1, w2, fmaf(xm2, w1, fmaf(xm3, w0, bias))));
            ob[j] = siluf(acc);
            xm3 = xm2; xm2 = xm1; xm1 = x;
            zb[j] = siluf(px[t * 512 + 256]);
        }
        *(float4*)&pxs[t0 + q4 * 4] = *(float4*)ob;
        *(float4*)&pzt[t0 + q4 * 4] = *(float4*)zb;
    }
}

// ---------------------------------------------------------------------------
// K3: x_proj GEMM  (XST K-major [d][t]  @ WTxp [256,40->64])
// ---------------------------------------------------------------------------
__global__ void k_gemm_xp() {
    __shared__ float As[64][65];
    __shared__ float Ws[64][64];
    int tt = blockIdx.y;
    int ib = blockIdx.z;
    int i = ib >> 2;
    int T = scanT(i);
    if (tt * 64 >= T) return;
    int t0 = tt * 64;
    int SB = c_TB[ib];
    int tid = threadIdx.x;
    int tx = tid & 15, ty = tid >> 4;
    float acc[4][4] = {};
    for (int kc = 0; kc < 4; kc++) {
        for (int p = 0; p < 16; p++) {
            int idx = p * 256 + tid;
            int m = idx & 63, kk = idx >> 6;   // m(t) fast: coalesced
            As[kk][m] = g_XST[SB * 256 + (kc * 64 + kk) * T + t0 + m];
        }
        for (int p = 0; p < 16; p++) {
            int idx = p * 256 + tid;
            int n = idx & 63, kk = idx >> 6;
            Ws[kk][n] = g_WTxp[(i * 256 + kc * 64 + kk) * 64 + n];
        }
        __syncthreads();
#pragma unroll
        for (int kk = 0; kk < 64; kk++) {
            float4 bv = *(const float4*)&Ws[kk][tx * 4];
            float av[4];
#pragma unroll
            for (int im = 0; im < 4; im++) av[im] = As[kk][ty * 4 + im];
#pragma unroll
            for (int im = 0; im < 4; im++) {
                acc[im][0] = fmaf(av[im], bv.x, acc[im][0]);
                acc[im][1] = fmaf(av[im], bv.y, acc[im][1]);
                acc[im][2] = fmaf(av[im], bv.z, acc[im][2]);
                acc[im][3] = fmaf(av[im], bv.w, acc[im][3]);
            }
        }
        __syncthreads();
    }
    if (tx < 10) {
#pragma unroll
        for (int im = 0; im < 4; im++) {
            int t = t0 + ty * 4 + im;
            float4 v = make_float4(acc[im][0], acc[im][1], acc[im][2], acc[im][3]);
            *(float4*)&g_XDBL[(SB + t) * 40 + tx * 4] = v;
        }
    }
}

// ---------------------------------------------------------------------------
// K4: dt_proj (K=8) + softplus -> DT [d][t].  thread=d, 64-t chunk.
// ---------------------------------------------------------------------------
__global__ void k_delta(const float* __restrict__ dtw, const float* __restrict__ dtb) {
    int tc = blockIdx.x, ib = blockIdx.y;
    int i = ib >> 2;
    int T = scanT(i);
    if (tc * 64 >= T) return;
    int d = threadIdx.x;
    int SB = c_TB[ib];
    float4 w0 = *(const float4*)&dtw[(i * 256 + d) * 8];
    float4 w1 = *(const float4*)&dtw[(i * 256 + d) * 8 + 4];
    float bias = dtb[i * 256 + d];
    float* pDT = &g_DT[SB * 256 + d * T];
    int t0 = tc * 64;
    for (int q4 = 0; q4 < 16; q4++) {
        float buf[4];
#pragma unroll
        for (int j = 0; j < 4; j++) {
            int t = t0 + q4 * 4 + j;
            const float4* r = (const float4*)&g_XDBL[(SB + t) * 40];
            float4 a0 = r[0], a1 = r[1];
            float pre = bias;
            pre = fmaf(a0.x, w0.x, pre); pre = fmaf(a0.y, w0.y, pre);
            pre = fmaf(a0.z, w0.z, pre); pre = fmaf(a0.w, w0.w, pre);
            pre = fmaf(a1.x, w1.x, pre); pre = fmaf(a1.y, w1.y, pre);
            pre = fmaf(a1.z, w1.z, pre); pre = fmaf(a1.w, w1.w, pre);
            buf[j] = (pre > 15.0f) ? pre : __logf(1.0f + __expf(pre));
        }
        *(float4*)&pDT[t0 + q4 * 4] = *(float4*)buf;
    }
}

// ---------------------------------------------------------------------------
// K5a: chunk-local scan: per (ib, chunk, d) compute hL[16], P[16]
// ---------------------------------------------------------------------------
__global__ void k_scan1(const float* __restrict__ alog) {
    int c = blockIdx.x, ib = blockIdx.y;
    int i = ib >> 2;
    int T = scanT(i);
    int LC = T >> 4;
    int d = threadIdx.x;
    int SB = c_TB[ib];
    bool pw = (g_powBad == 0);
    float A0 = -__expf(alog[(i * 256 + d) * 16]);
    const float* pD = &g_DT[SB * 256 + d * T];
    const float* pU = &g_XST[SB * 256 + d * T];
    const float* pBC = &g_XDBL[SB * 40];
    float h[16];
#pragma unroll
    for (int s = 0; s < 16; s++) h[s] = 0.0f;
    float dsum = 0.0f;
    int t0 = c * LC;
    if (pw) {
        for (int tt = t0; tt < t0 + LC; tt += 4) {
            float dva[4], uva[4];
            *(float4*)dva = *(const float4*)&pD[tt];
            *(float4*)uva = *(const float4*)&pU[tt];
#pragma unroll
            for (int j = 0; j < 4; j++) {
                float dv = dva[j];
                float du = dv * uva[j];
                dsum += dv;
                float q = __expf(dv * A0);
                const float4* B4 = (const float4*)&pBC[(tt + j) * 40 + 8];
                float4 B0 = B4[0], B1 = B4[1], B2 = B4[2], B3 = B4[3];
                float ap = q;
                h[0]  = fmaf(ap, h[0],  du * B0.x); ap *= q;
                h[1]  = fmaf(ap, h[1],  du * B0.y); ap *= q;
                h[2]  = fmaf(ap, h[2],  du * B0.z); ap *= q;
                h[3]  = fmaf(ap, h[3],  du * B0.w); ap *= q;
                h[4]  = fmaf(ap, h[4],  du * B1.x); ap *= q;
                h[5]  = fmaf(ap, h[5],  du * B1.y); ap *= q;
                h[6]  = fmaf(ap, h[6],  du * B1.z); ap *= q;
                h[7]  = fmaf(ap, h[7],  du * B1.w); ap *= q;
                h[8]  = fmaf(ap, h[8],  du * B2.x); ap *= q;
                h[9]  = fmaf(ap, h[9],  du * B2.y); ap *= q;
                h[10] = fmaf(ap, h[10], du * B2.z); ap *= q;
                h[11] = fmaf(ap, h[11], du * B2.w); ap *= q;
                h[12] = fmaf(ap, h[12], du * B3.x); ap *= q;
                h[13] = fmaf(ap, h[13], du * B3.y); ap *= q;
                h[14] = fmaf(ap, h[14], du * B3.z); ap *= q;
                h[15] = fmaf(ap, h[15], du * B3.w);
            }
        }
    } else {
        float As[16];
#pragma unroll
        for (int s = 0; s < 16; s++) As[s] = -__expf(alog[(i * 256 + d) * 16 + s]);
        for (int tt = t0; tt < t0 + LC; tt += 4) {
            float dva[4], uva[4];
            *(float4*)dva = *(const float4*)&pD[tt];
            *(float4*)uva = *(const float4*)&pU[tt];
#pragma unroll
            for (int j = 0; j < 4; j++) {
                float dv = dva[j];
                float du = dv * uva[j];
                dsum += dv;
                const float* Bp = &pBC[(tt + j) * 40 + 8];
#pragma unroll
                for (int s = 0; s < 16; s++) {
                    float a = __expf(dv * As[s]);
                    h[s] = fmaf(a, h[s], du * Bp[s]);
                }
            }
        }
    }
    int base = ((ib * NCHUNK + c) * 256 + d) * 16;
#pragma unroll
    for (int s = 0; s < 16; s++) {
        float Ascale = pw ? (A0 * (float)(s + 1))
                          : (-__expf(alog[(i * 256 + d) * 16 + s]));
        g_CP[base + s] = __expf(Ascale * dsum);
        g_CH[base + s] = h[s];
    }
}

// ---------------------------------------------------------------------------
// K5b: prefix over chunks: h_init per (ib, chunk, d, s)
// ---------------------------------------------------------------------------
__global__ void k_scan2() {
    int g = blockIdx.x * 256 + threadIdx.x;   // 65536 threads
    int ib = g >> 12;
    int rem = g & 4095;                        // d*16+s
    float hi = 0.0f;
    for (int c = 0; c < NCHUNK; c++) {
        int idx = ib * (NCHUNK * 4096) + c * 4096 + rem;
        g_HI[idx] = hi;
        hi = fmaf(g_CP[idx], hi, g_CH[idx]);
    }
}

// ---------------------------------------------------------------------------
// K5c: chunk recompute with true h_init; emit y -> YT [d][t]
// ---------------------------------------------------------------------------
__global__ void k_scan3(const float* __restrict__ alog, const float* __restrict__ Dv) {
    int c = blockIdx.x, ib = blockIdx.y;
    int i = ib >> 2;
    int T = scanT(i);
    int LC = T >> 4;
    int d = threadIdx.x;
    int SB = c_TB[ib];
    bool pw = (g_powBad == 0);
    float A0 = -__expf(alog[(i * 256 + d) * 16]);
    float Dreg = Dv[i * 256 + d];
    const float* pD = &g_DT[SB * 256 + d * T];
    const float* pU = &g_XST[SB * 256 + d * T];
    const float* pZ = &g_ZT[SB * 256 + d * T];
    const float* pBC = &g_XDBL[SB * 40];
    float* pY = &g_YT[SB * 256 + d * T];
    float h[16];
    {
        int base = ((ib * NCHUNK + c) * 256 + d) * 16;
#pragma unroll
        for (int s = 0; s < 16; s++) h[s] = g_HI[base + s];
    }
    int t0 = c * LC;
    if (pw) {
        for (int tt = t0; tt < t0 + LC; tt += 4) {
            float dva[4], uva[4], zva[4], yb[4];
            *(float4*)dva = *(const float4*)&pD[tt];
            *(float4*)uva = *(const float4*)&pU[tt];
            *(float4*)zva = *(const float4*)&pZ[tt];
#pragma unroll
            for (int j = 0; j < 4; j++) {
                float dv = dva[j];
                float u = uva[j];
                float du = dv * u;
                float q = __expf(dv * A0);
                const float4* B4 = (const float4*)&pBC[(tt + j) * 40 + 8];
                float4 B0 = B4[0], B1 = B4[1], B2 = B4[2], B3 = B4[3];
                float4 C0 = B4[4], C1 = B4[5], C2 = B4[6], C3 = B4[7];
                float ys = 0.0f;
                float ap = q;
                h[0]  = fmaf(ap, h[0],  du * B0.x); ys = fmaf(h[0],  C0.x, ys); ap *= q;
                h[1]  = fmaf(ap, h[1],  du * B0.y); ys = fmaf(h[1],  C0.y, ys); ap *= q;
                h[2]  = fmaf(ap, h[2],  du * B0.z); ys = fmaf(h[2],  C0.z, ys); ap *= q;
                h[3]  = fmaf(ap, h[3],  du * B0.w); ys = fmaf(h[3],  C0.w, ys); ap *= q;
                h[4]  = fmaf(ap, h[4],  du * B1.x); ys = fmaf(h[4],  C1.x, ys); ap *= q;
                h[5]  = fmaf(ap, h[5],  du * B1.y); ys = fmaf(h[5],  C1.y, ys); ap *= q;
                h[6]  = fmaf(ap, h[6],  du * B1.z); ys = fmaf(h[6],  C1.z, ys); ap *= q;
                h[7]  = fmaf(ap, h[7],  du * B1.w); ys = fmaf(h[7],  C1.w, ys); ap *= q;
                h[8]  = fmaf(ap, h[8],  du * B2.x); ys = fmaf(h[8],  C2.x, ys); ap *= q;
                h[9]  = fmaf(ap, h[9],  du * B2.y); ys = fmaf(h[9],  C2.y, ys); ap *= q;
                h[10] = fmaf(ap, h[10], du * B2.z); ys = fmaf(h[10], C2.z, ys); ap *= q;
                h[11] = fmaf(ap, h[11], du * B2.w); ys = fmaf(h[11], C2.w, ys); ap *= q;
                h[12] = fmaf(ap, h[12], du * B3.x); ys = fmaf(h[12], C3.x, ys); ap *= q;
                h[13] = fmaf(ap, h[13], du * B3.y); ys = fmaf(h[13], C3.y, ys); ap *= q;
                h[14] = fmaf(ap, h[14], du * B3.z); ys = fmaf(h[14], C3.z, ys); ap *= q;
                h[15] = fmaf(ap, h[15], du * B3.w); ys = fmaf(h[15], C3.w, ys);
                yb[j] = fmaf(u, Dreg, ys) * zva[j];
            }
            *(float4*)&pY[tt] = *(float4*)yb;
        }
    } else {
        float As[16];
#pragma unroll
        for (int s = 0; s < 16; s++) As[s] = -__expf(alog[(i * 256 + d) * 16 + s]);
        for (int tt = t0; tt < t0 + LC; tt += 4) {
            float dva[4], uva[4], zva[4], yb[4];
            *(float4*)dva = *(const float4*)&pD[tt];
            *(float4*)uva = *(const float4*)&pU[tt];
            *(float4*)zva = *(const float4*)&pZ[tt];
#pragma unroll
            for (int j = 0; j < 4; j++) {
                float dv = dva[j];
                float u = uva[j];
                float du = dv * u;
                const float* Bp = &pBC[(tt + j) * 40 + 8];
                float ys = 0.0f;
#pragma unroll
                for (int s = 0; s < 16; s++) {
                    float a = __expf(dv * As[s]);
                    h[s] = fmaf(a, h[s], du * Bp[s]);
                    ys = fmaf(h[s], Bp[16 + s], ys);
                }
                yb[j] = fmaf(u, Dreg, ys) * zva[j];
            }
            *(float4*)&pY[tt] = *(float4*)yb;
        }
    }
}

// ---------------------------------------------------------------------------
// K6: out_proj GEMM  (YT [d][t] K-major  @  WTout [256][128])
// ---------------------------------------------------------------------------
__global__ void k_gemm_out() {
    __shared__ float As[64][65];
    __shared__ float Ws[64][64];
    int nt = blockIdx.x;
    int tt = blockIdx.y;
    int ib = blockIdx.z;
    int i = ib >> 2;
    int T = scanT(i);
    if (tt * 64 >= T) return;
    int t0 = tt * 64;
    int SB = c_TB[ib];
    int tid = threadIdx.x;
    int tx = tid & 15, ty = tid >> 4;
    float acc[4][4] = {};
    for (int kc = 0; kc < 4; kc++) {
        for (int p = 0; p < 16; p++) {
            int idx = p * 256 + tid;
            int m = idx & 63, kk = idx >> 6;
            As[kk][m] = g_YT[SB * 256 + (kc * 64 + kk) * T + t0 + m];
        }
        for (int p = 0; p < 16; p++) {
            int idx = p * 256 + tid;
            int n = idx & 63, kk = idx >> 6;
            Ws[kk][n] = g_WTout[(i * 256 + kc * 64 + kk) * 128 + nt * 64 + n];
        }
        __syncthreads();
#pragma unroll
        for (int kk = 0; kk < 64; kk++) {
            float4 bv = *(const float4*)&Ws[kk][tx * 4];
            float av[4];
#pragma unroll
            for (int im = 0; im < 4; im++) av[im] = As[kk][ty * 4 + im];
#pragma unroll
            for (int im = 0; im < 4; im++) {
                acc[im][0] = fmaf(av[im], bv.x, acc[im][0]);
                acc[im][1] = fmaf(av[im], bv.y, acc[im][1]);
                acc[im][2] = fmaf(av[im], bv.z, acc[im][2]);
                acc[im][3] = fmaf(av[im], bv.w, acc[im][3]);
            }
        }
        __syncthreads();
    }
#pragma unroll
    for (int im = 0; im < 4; im++) {
        int t = t0 + ty * 4 + im;
        float4 v = make_float4(acc[im][0], acc[im][1], acc[im][2], acc[im][3]);
        *(float4*)&g_OUT[(SB + t) * 128 + nt * 64 + tx * 4] = v;
    }
}

// interp of backward-scan output (len 4096 -> index 8191-l of the len-8192 signal)
__device__ __forceinline__ float interp_flip(int i, int b, int l, int c) {
    float pos = 0.5f * (float)(8191 - l) - 0.25f;
    pos = fminf(fmaxf(pos, 0.0f), 4095.0f);
    int lo = (int)floorf(pos);
    int hi = min(lo + 1, 4095);
    float w = pos - (float)lo;
    const float* ob = &g_OUT[c_TB[i * 4 + b] * 128 + c];
    return ob[lo * 128] * (1.0f - w) + ob[hi * 128] * w;
}

// ---------------------------------------------------------------------------
// K7: merge 4 scan outputs -> a,b maps [2][B][C][64][64] (smem transpose)
// ---------------------------------------------------------------------------
__global__ void k_merge() {
    __shared__ float S[64][129];
    int irow = blockIdx.x;
    int b = blockIdx.y;
    int tid = threadIdx.x;
    for (int half = 0; half < 2; half++) {
        for (int p = 0; p < 32; p++) {
            int idx = p * 256 + tid;
            int c = idx & 127, j = idx >> 7;
            int l  = irow * 128 + j + (half ? 64 : 0);
            int l2 = j * 128 + irow + (half ? 64 : 0);
            float v = g_OUT[(c_TB[b] + l) * 128 + c];
            v += interp_flip(1, b, l, c);
            v += g_OUT[(c_TB[8 + b] + l2) * 128 + c];
            v += interp_flip(3, b, l2, c);
            S[j][c] = v;
        }
        __syncthreads();
        for (int p = 0; p < 32; p++) {
            int idx = p * 256 + tid;
            int j = idx & 63, c = idx >> 6;
            g_AB[((half * 4 + b) * 128 + c) * 4096 + irow * 64 + j] = S[j][c];
        }
        __syncthreads();
    }
}

// ---------------------------------------------------------------------------
// K8: bilinear 64->128 upsample of a and b, + feat_a + feat_b
// ---------------------------------------------------------------------------
__global__ void k_final(const float* __restrict__ fa, const float* __restrict__ fb,
                        float* __restrict__ out) {
    int idx = blockIdx.x * 256 + threadIdx.x;
    int w = idx & 127, hh = (idx >> 7) & 127, c = (idx >> 14) & 127, b = idx >> 21;
    float ph = fminf(fmaxf(0.5f * hh - 0.25f, 0.0f), 63.0f);
    int h0 = (int)floorf(ph); int h1 = min(h0 + 1, 63); float wh = ph - (float)h0;
    float pw = fminf(fmaxf(0.5f * w - 0.25f, 0.0f), 63.0f);
    int w0 = (int)floorf(pw); int w1 = min(w0 + 1, 63); float ww = pw - (float)w0;
    const float* Aa = &g_AB[((0 * 4 + b) * 128 + c) * 4096];
    const float* Bb = &g_AB[((1 * 4 + b) * 128 + c) * 4096];
    float av = (Aa[h0 * 64 + w0] * (1.0f - ww) + Aa[h0 * 64 + w1] * ww) * (1.0f - wh)
             + (Aa[h1 * 64 + w0] * (1.0f - ww) + Aa[h1 * 64 + w1] * ww) * wh;
    float bv = (Bb[h0 * 64 + w0] * (1.0f - ww) + Bb[h0 * 64 + w1] * ww) * (1.0f - wh)
             + (Bb[h1 * 64 + w0] * (1.0f - ww) + Bb[h1 * 64 + w1] * ww) * wh;
    out[idx] = av + bv + fa[idx] + fb[idx];
}

// ---------------------------------------------------------------------------
extern "C" void kernel_launch(void* const* d_in, const int* in_sizes, int n_in,
                              void* d_out, int out_size) {
    (void)in_sizes; (void)n_in; (void)out_size;
    const float* fa   = (const float*)d_in[0];
    const float* fb   = (const float*)d_in[1];
    const float* inw  = (const float*)d_in[2];
    const float* cw   = (const float*)d_in[3];
    const float* cb   = (const float*)d_in[4];
    const float* xpw  = (const float*)d_in[5];
    const float* dtw  = (const float*)d_in[6];
    const float* dtb  = (const float*)d_in[7];
    const float* alog = (const float*)d_in[8];
    const float* Dv   = (const float*)d_in[9];
    const float* outw = (const float*)d_in[10];
    float* out = (float*)d_out;

    k_reset<<<1, 1>>>();
    k_prep<<<1024, 256>>>(inw, xpw, outw, alog);
    k_gemm_in<<<dim3(8, 128, 16), 256>>>(fa, fb);
    k_conv<<<dim3(128, 16), 256>>>(cw, cb);
    k_gemm_xp<<<dim3(1, 128, 16), 256>>>();
    k_delta<<<dim3(128, 16), 256>>>(dtw, dtb);
    k_scan1<<<dim3(NCHUNK, 16), 256>>>(alog);
    k_scan2<<<256, 256>>>();
    k_scan3<<<dim3(NCHUNK, 16), 256>>>(alog, Dv);
    k_gemm_out<<<dim3(2, 128, 16), 256>>>();
    k_merge<<<dim3(64, 4), 256>>>();
    k_final<<<32768, 256>>>(fa, fb, out);
}

// round 6
// speedup vs baseline: 3.3115x; 1.4398x over previous
#include <cuda_runtime.h>
#include <math.h>

// ---------------------------------------------------------------------------
// JointMambaFusion: B=4, C=128, H=W=128, D_INNER=256, D_STATE=16, DT_RANK=8
// 4 scans: T = {8192, 4096, 8192, 4096}; 16 (scan,batch) sequences, compact
// token bases c_TB[ib], total TOKTOT = 98304 tokens.
// All intermediates token-major [t][d] (coalesced for thread=d kernels).
// ---------------------------------------------------------------------------

#define TOKTOT 98304
#define NCHUNK 32

__constant__ int c_TB[16] = {
    0,     8192,  16384, 24576,      // i=0 (T=8192)
    32768, 36864, 40960, 45056,      // i=1 (T=4096)
    49152, 57344, 65536, 73728,      // i=2 (T=8192)
    81920, 86016, 90112, 94208       // i=3 (T=4096)
};

// scratch (device globals; ~510 MB total)
__device__ float g_XZ   [TOKTOT * 512];   // in_proj output: xl | z (raw)
__device__ float g_XS   [TOKTOT * 256];   // u = silu(conv(xl)), token-major
__device__ float g_XDBL [TOKTOT * 40];    // dt(8) | B(16) | C(16), token-major
__device__ float g_YT   [TOKTOT * 256];   // scan output y, token-major
__device__ float g_OUT  [TOKTOT * 128];   // out_proj output, token-major
__device__ float g_AB   [2 * 4 * 128 * 64 * 64];
__device__ float g_WTin [4 * 128 * 512];  // in_proj_w transposed  [c][e]
__device__ float g_WTxp [4 * 256 * 64];   // x_proj_w transposed, zero-padded
__device__ float g_WTout[4 * 256 * 128];  // out_proj_w transposed [d][o]
// chunked-scan state: [ib][chunk][d][s]
__device__ float g_CP [16 * NCHUNK * 256 * 16];
__device__ float g_CH [16 * NCHUNK * 256 * 16];
__device__ float g_HI [16 * NCHUNK * 256 * 16];
__device__ int   g_powBad;

__device__ __forceinline__ int scanT(int i) { return (i & 1) ? 4096 : 8192; }

__device__ __forceinline__ float siluf(float x) {
    return __fdividef(x, 1.0f + __expf(-x));
}

__device__ __forceinline__ float softplusf(float x) {
    return (x > 15.0f) ? x : __logf(1.0f + __expf(x));
}

// scan-direction gather: x_i[b, t, c] from feat_a / feat_b
__device__ __forceinline__ float gather_x(int i, int b, int t, int c,
                                          const float* __restrict__ fa,
                                          const float* __restrict__ fb) {
    int l = (i & 1) ? (8191 - 2 * t) : t;
    int base = (b * 128 + c) * 128;
    if (i < 2) {
        int hh = l >> 7, ww = l & 127;
        if (ww < 64) return fa[(base + 2 * hh) * 128 + 2 * ww];
        else         return fb[(base + 2 * hh) * 128 + 2 * ww - 128];
    } else {
        int ww = l >> 7, rr = l & 127;
        if (rr < 64) return fa[(base + 2 * rr) * 128 + 2 * ww];
        else         return fb[(base + 2 * rr - 128) * 128 + 2 * ww];
    }
}

// ---------------------------------------------------------------------------
__global__ void k_reset() { g_powBad = 0; }

// K0: transpose weights + verify A_s = (s+1)*A_0 structure
__global__ void k_prep(const float* __restrict__ inw,
                       const float* __restrict__ xpw,
                       const float* __restrict__ outw,
                       const float* __restrict__ alog) {
    int idx = blockIdx.x * 256 + threadIdx.x;
    if (idx < 4 * 512 * 128) {        // WTin[i][c][e] = inw[i][e][c]
        int i = idx / (512 * 128), r = idx % (512 * 128);
        int e = r / 128, c = r % 128;
        g_WTin[(i * 128 + c) * 512 + e] = inw[idx];
    }
    if (idx < 4 * 256 * 64) {         // WTxp[i][c][e] (e<40 valid, else 0)
        int i = idx / (256 * 64), r = idx % (256 * 64);
        int c = r / 64, e = r % 64;
        g_WTxp[idx] = (e < 40) ? xpw[(i * 40 + e) * 256 + c] : 0.0f;
    }
    if (idx < 4 * 256 * 128) {        // WTout[i][c][o] = outw[i][o][c]
        int i = idx / (256 * 128), r = idx % (256 * 128);
        int c = r / 128, o = r % 128;
        g_WTout[idx] = outw[(i * 128 + o) * 256 + c];
    }
    if (idx < 4 * 256 * 16) {         // structure check
        int s = idx & 15;
        int dI = idx >> 4;
        float As = -__expf(alog[dI * 16 + s]);
        float A0 = -__expf(alog[dI * 16]);
        float ratio = As / A0;
        if (fabsf(ratio - (float)(s + 1)) > 1e-5f * (float)(s + 1))
            atomicOr(&g_powBad, 1);
    }
}

// ---------------------------------------------------------------------------
// K1: in_proj GEMM (gather fused into A-tile load).  K=128, N=512.
// ---------------------------------------------------------------------------
__global__ void k_gemm_in(const float* __restrict__ fa, const float* __restrict__ fb) {
    __shared__ float As[64][65];
    __shared__ float Ws[64][64];
    int nt = blockIdx.x;
    int tt = blockIdx.y;
    int ib = blockIdx.z;
    int i = ib >> 2, b = ib & 3;
    int T = scanT(i);
    if (tt * 64 >= T) return;
    int t0 = tt * 64;
    int tid = threadIdx.x;
    int tx = tid & 15, ty = tid >> 4;
    float acc[4][4] = {};
    for (int kc = 0; kc < 2; kc++) {
        for (int p = 0; p < 16; p++) {
            int idx = p * 256 + tid;
            int m = idx & 63, kk = idx >> 6;
            As[kk][m] = gather_x(i, b, t0 + m, kc * 64 + kk, fa, fb);
        }
        for (int p = 0; p < 16; p++) {
            int idx = p * 256 + tid;
            int n = idx & 63, kk = idx >> 6;
            Ws[kk][n] = g_WTin[(i * 128 + kc * 64 + kk) * 512 + nt * 64 + n];
        }
        __syncthreads();
#pragma unroll
        for (int kk = 0; kk < 64; kk++) {
            float4 bv = *(const float4*)&Ws[kk][tx * 4];
            float av[4];
#pragma unroll
            for (int im = 0; im < 4; im++) av[im] = As[kk][ty * 4 + im];
#pragma unroll
            for (int im = 0; im < 4; im++) {
                acc[im][0] = fmaf(av[im], bv.x, acc[im][0]);
                acc[im][1] = fmaf(av[im], bv.y, acc[im][1]);
                acc[im][2] = fmaf(av[im], bv.z, acc[im][2]);
                acc[im][3] = fmaf(av[im], bv.w, acc[im][3]);
            }
        }
        __syncthreads();
    }
    int SB = c_TB[ib];
#pragma unroll
    for (int im = 0; im < 4; im++) {
        int t = t0 + ty * 4 + im;
        float4 v = make_float4(acc[im][0], acc[im][1], acc[im][2], acc[im][3]);
        *(float4*)&g_XZ[(SB + t) * 512 + nt * 64 + tx * 4] = v;
    }
}

// ---------------------------------------------------------------------------
// K2: causal conv(4)+silu -> XS token-major.  thread=d, 64-t chunk, coalesced.
// ---------------------------------------------------------------------------
__global__ void k_conv(const float* __restrict__ cw, const float* __restrict__ cb) {
    int tc = blockIdx.x, ib = blockIdx.y;
    int i = ib >> 2;
    int T = scanT(i);
    if (tc * 64 >= T) return;
    int d = threadIdx.x;
    int SB = c_TB[ib];
    const float* w = &cw[(i * 256 + d) * 4];
    float w0 = w[0], w1 = w[1], w2 = w[2], w3 = w[3];
    float bias = cb[i * 256 + d];
    const float* px = &g_XZ[SB * 512 + d];
    float* pxs = &g_XS[SB * 256 + d];
    int t0 = tc * 64;
    float xm1 = (t0 >= 1) ? px[(t0 - 1) * 512] : 0.0f;
    float xm2 = (t0 >= 2) ? px[(t0 - 2) * 512] : 0.0f;
    float xm3 = (t0 >= 3) ? px[(t0 - 3) * 512] : 0.0f;
    for (int q4 = 0; q4 < 16; q4++) {
        float xv[4];
#pragma unroll
        for (int j = 0; j < 4; j++) xv[j] = px[(t0 + q4 * 4 + j) * 512];
#pragma unroll
        for (int j = 0; j < 4; j++) {
            float x = xv[j];
            float acc = fmaf(x, w3, fmaf(xm1, w2, fmaf(xm2, w1, fmaf(xm3, w0, bias))));
            pxs[(t0 + q4 * 4 + j) * 256] = siluf(acc);
            xm3 = xm2; xm2 = xm1; xm1 = x;
        }
    }
}

// ---------------------------------------------------------------------------
// K3: x_proj GEMM  (XS token-major, kk-fast coalesced A load)
// ---------------------------------------------------------------------------
__global__ void k_gemm_xp() {
    __shared__ float As[64][65];
    __shared__ float Ws[64][64];
    int tt = blockIdx.y;
    int ib = blockIdx.z;
    int i = ib >> 2;
    int T = scanT(i);
    if (tt * 64 >= T) return;
    int t0 = tt * 64;
    int SB = c_TB[ib];
    int tid = threadIdx.x;
    int tx = tid & 15, ty = tid >> 4;
    float acc[4][4] = {};
    for (int kc = 0; kc < 4; kc++) {
        for (int p = 0; p < 16; p++) {
            int idx = p * 256 + tid;
            int kk = idx & 63, m = idx >> 6;   // kk fast -> coalesced global read
            As[kk][m] = g_XS[(SB + t0 + m) * 256 + kc * 64 + kk];
        }
        for (int p = 0; p < 16; p++) {
            int idx = p * 256 + tid;
            int n = idx & 63, kk = idx >> 6;
            Ws[kk][n] = g_WTxp[(i * 256 + kc * 64 + kk) * 64 + n];
        }
        __syncthreads();
#pragma unroll
        for (int kk = 0; kk < 64; kk++) {
            float4 bv = *(const float4*)&Ws[kk][tx * 4];
            float av[4];
#pragma unroll
            for (int im = 0; im < 4; im++) av[im] = As[kk][ty * 4 + im];
#pragma unroll
            for (int im = 0; im < 4; im++) {
                acc[im][0] = fmaf(av[im], bv.x, acc[im][0]);
                acc[im][1] = fmaf(av[im], bv.y, acc[im][1]);
                acc[im][2] = fmaf(av[im], bv.z, acc[im][2]);
                acc[im][3] = fmaf(av[im], bv.w, acc[im][3]);
            }
        }
        __syncthreads();
    }
    if (tx < 10) {
#pragma unroll
        for (int im = 0; im < 4; im++) {
            int t = t0 + ty * 4 + im;
            float4 v = make_float4(acc[im][0], acc[im][1], acc[im][2], acc[im][3]);
            *(float4*)&g_XDBL[(SB + t) * 40 + tx * 4] = v;
        }
    }
}

// ---------------------------------------------------------------------------
// K5a: chunk-local scan (delta fused inline). thread=d.
// ---------------------------------------------------------------------------
__global__ void k_scan1(const float* __restrict__ alog,
                        const float* __restrict__ dtw, const float* __restrict__ dtb) {
    int c = blockIdx.x, ib = blockIdx.y;
    int i = ib >> 2;
    int T = scanT(i);
    int LC = T / NCHUNK;
    int d = threadIdx.x;
    int SB = c_TB[ib];
    bool pw = (g_powBad == 0);
    float A0 = -__expf(alog[(i * 256 + d) * 16]);
    float4 dw0 = *(const float4*)&dtw[(i * 256 + d) * 8];
    float4 dw1 = *(const float4*)&dtw[(i * 256 + d) * 8 + 4];
    float dbias = dtb[i * 256 + d];
    const float* pU = &g_XS[SB * 256 + d];
    const float* pBC = &g_XDBL[SB * 40];
    float h[16];
#pragma unroll
    for (int s = 0; s < 16; s++) h[s] = 0.0f;
    float dsum = 0.0f;
    int t0 = c * LC;
    if (pw) {
#pragma unroll 2
        for (int t = t0; t < t0 + LC; t++) {
            const float4* r = (const float4*)&pBC[t * 40];
            float4 a0 = r[0], a1 = r[1];
            float pre = dbias;
            pre = fmaf(a0.x, dw0.x, pre); pre = fmaf(a0.y, dw0.y, pre);
            pre = fmaf(a0.z, dw0.z, pre); pre = fmaf(a0.w, dw0.w, pre);
            pre = fmaf(a1.x, dw1.x, pre); pre = fmaf(a1.y, dw1.y, pre);
            pre = fmaf(a1.z, dw1.z, pre); pre = fmaf(a1.w, dw1.w, pre);
            float dv = softplusf(pre);
            float du = dv * pU[t * 256];
            dsum += dv;
            float q = __expf(dv * A0);
            float4 B0 = r[2], B1 = r[3], B2 = r[4], B3 = r[5];
            float ap = q;
            h[0]  = fmaf(ap, h[0],  du * B0.x); ap *= q;
            h[1]  = fmaf(ap, h[1],  du * B0.y); ap *= q;
            h[2]  = fmaf(ap, h[2],  du * B0.z); ap *= q;
            h[3]  = fmaf(ap, h[3],  du * B0.w); ap *= q;
            h[4]  = fmaf(ap, h[4],  du * B1.x); ap *= q;
            h[5]  = fmaf(ap, h[5],  du * B1.y); ap *= q;
            h[6]  = fmaf(ap, h[6],  du * B1.z); ap *= q;
            h[7]  = fmaf(ap, h[7],  du * B1.w); ap *= q;
            h[8]  = fmaf(ap, h[8],  du * B2.x); ap *= q;
            h[9]  = fmaf(ap, h[9],  du * B2.y); ap *= q;
            h[10] = fmaf(ap, h[10], du * B2.z); ap *= q;
            h[11] = fmaf(ap, h[11], du * B2.w); ap *= q;
            h[12] = fmaf(ap, h[12], du * B3.x); ap *= q;
            h[13] = fmaf(ap, h[13], du * B3.y); ap *= q;
            h[14] = fmaf(ap, h[14], du * B3.z); ap *= q;
            h[15] = fmaf(ap, h[15], du * B3.w);
        }
    } else {
        float As[16];
#pragma unroll
        for (int s = 0; s < 16; s++) As[s] = -__expf(alog[(i * 256 + d) * 16 + s]);
        for (int t = t0; t < t0 + LC; t++) {
            const float4* r = (const float4*)&pBC[t * 40];
            float4 a0 = r[0], a1 = r[1];
            float pre = dbias;
            pre = fmaf(a0.x, dw0.x, pre); pre = fmaf(a0.y, dw0.y, pre);
            pre = fmaf(a0.z, dw0.z, pre); pre = fmaf(a0.w, dw0.w, pre);
            pre = fmaf(a1.x, dw1.x, pre); pre = fmaf(a1.y, dw1.y, pre);
            pre = fmaf(a1.z, dw1.z, pre); pre = fmaf(a1.w, dw1.w, pre);
            float dv = softplusf(pre);
            float du = dv * pU[t * 256];
            dsum += dv;
            const float* Bp = &pBC[t * 40 + 8];
#pragma unroll
            for (int s = 0; s < 16; s++) {
                float a = __expf(dv * As[s]);
                h[s] = fmaf(a, h[s], du * Bp[s]);
            }
        }
    }
    int base = ((ib * NCHUNK + c) * 256 + d) * 16;
#pragma unroll
    for (int s = 0; s < 16; s++) {
        float Ascale = pw ? (A0 * (float)(s + 1))
                          : (-__expf(alog[(i * 256 + d) * 16 + s]));
        g_CP[base + s] = __expf(Ascale * dsum);
        g_CH[base + s] = h[s];
    }
}

// ---------------------------------------------------------------------------
// K5b: prefix over chunks
// ---------------------------------------------------------------------------
__global__ void k_scan2() {
    int g = blockIdx.x * 256 + threadIdx.x;   // 65536 threads
    int ib = g >> 12;
    int rem = g & 4095;                        // d*16+s
    float hi = 0.0f;
    for (int c = 0; c < NCHUNK; c++) {
        int idx = ib * (NCHUNK * 4096) + c * 4096 + rem;
        g_HI[idx] = hi;
        hi = fmaf(g_CP[idx], hi, g_CH[idx]);
    }
}

// ---------------------------------------------------------------------------
// K5c: chunk recompute with true h_init; y -> YT token-major (coalesced)
// ---------------------------------------------------------------------------
__global__ void k_scan3(const float* __restrict__ alog, const float* __restrict__ Dv,
                        const float* __restrict__ dtw, const float* __restrict__ dtb) {
    int c = blockIdx.x, ib = blockIdx.y;
    int i = ib >> 2;
    int T = scanT(i);
    int LC = T / NCHUNK;
    int d = threadIdx.x;
    int SB = c_TB[ib];
    bool pw = (g_powBad == 0);
    float A0 = -__expf(alog[(i * 256 + d) * 16]);
    float Dreg = Dv[i * 256 + d];
    float4 dw0 = *(const float4*)&dtw[(i * 256 + d) * 8];
    float4 dw1 = *(const float4*)&dtw[(i * 256 + d) * 8 + 4];
    float dbias = dtb[i * 256 + d];
    const float* pU = &g_XS[SB * 256 + d];
    const float* pZ = &g_XZ[SB * 512 + 256 + d];
    const float* pBC = &g_XDBL[SB * 40];
    float* pY = &g_YT[SB * 256 + d];
    float h[16];
    {
        int base = ((ib * NCHUNK + c) * 256 + d) * 16;
#pragma unroll
        for (int s = 0; s < 16; s++) h[s] = g_HI[base + s];
    }
    int t0 = c * LC;
    if (pw) {
#pragma unroll 2
        for (int t = t0; t < t0 + LC; t++) {
            const float4* r = (const float4*)&pBC[t * 40];
            float4 a0 = r[0], a1 = r[1];
            float pre = dbias;
            pre = fmaf(a0.x, dw0.x, pre); pre = fmaf(a0.y, dw0.y, pre);
            pre = fmaf(a0.z, dw0.z, pre); pre = fmaf(a0.w, dw0.w, pre);
            pre = fmaf(a1.x, dw1.x, pre); pre = fmaf(a1.y, dw1.y, pre);
            pre = fmaf(a1.z, dw1.z, pre); pre = fmaf(a1.w, dw1.w, pre);
            float dv = softplusf(pre);
            float u = pU[t * 256];
            float du = dv * u;
            float q = __expf(dv * A0);
            float4 B0 = r[2], B1 = r[3], B2 = r[4], B3 = r[5];
            float4 C0 = r[6], C1 = r[7], C2 = r[8], C3 = r[9];
            float ys = 0.0f;
            float ap = q;
            h[0]  = fmaf(ap, h[0],  du * B0.x); ys = fmaf(h[0],  C0.x, ys); ap *= q;
            h[1]  = fmaf(ap, h[1],  du * B0.y); ys = fmaf(h[1],  C0.y, ys); ap *= q;
            h[2]  = fmaf(ap, h[2],  du * B0.z); ys = fmaf(h[2],  C0.z, ys); ap *= q;
            h[3]  = fmaf(ap, h[3],  du * B0.w); ys = fmaf(h[3],  C0.w, ys); ap *= q;
            h[4]  = fmaf(ap, h[4],  du * B1.x); ys = fmaf(h[4],  C1.x, ys); ap *= q;
            h[5]  = fmaf(ap, h[5],  du * B1.y); ys = fmaf(h[5],  C1.y, ys); ap *= q;
            h[6]  = fmaf(ap, h[6],  du * B1.z); ys = fmaf(h[6],  C1.z, ys); ap *= q;
            h[7]  = fmaf(ap, h[7],  du * B1.w); ys = fmaf(h[7],  C1.w, ys); ap *= q;
            h[8]  = fmaf(ap, h[8],  du * B2.x); ys = fmaf(h[8],  C2.x, ys); ap *= q;
            h[9]  = fmaf(ap, h[9],  du * B2.y); ys = fmaf(h[9],  C2.y, ys); ap *= q;
            h[10] = fmaf(ap, h[10], du * B2.z); ys = fmaf(h[10], C2.z, ys); ap *= q;
            h[11] = fmaf(ap, h[11], du * B2.w); ys = fmaf(h[11], C2.w, ys); ap *= q;
            h[12] = fmaf(ap, h[12], du * B3.x); ys = fmaf(h[12], C3.x, ys); ap *= q;
            h[13] = fmaf(ap, h[13], du * B3.y); ys = fmaf(h[13], C3.y, ys); ap *= q;
            h[14] = fmaf(ap, h[14], du * B3.z); ys = fmaf(h[14], C3.z, ys); ap *= q;
            h[15] = fmaf(ap, h[15], du * B3.w); ys = fmaf(h[15], C3.w, ys);
            float z = siluf(pZ[t * 512]);
            pY[t * 256] = fmaf(u, Dreg, ys) * z;
        }
    } else {
        float As[16];
#pragma unroll
        for (int s = 0; s < 16; s++) As[s] = -__expf(alog[(i * 256 + d) * 16 + s]);
        for (int t = t0; t < t0 + LC; t++) {
            const float4* r = (const float4*)&pBC[t * 40];
            float4 a0 = r[0], a1 = r[1];
            float pre = dbias;
            pre = fmaf(a0.x, dw0.x, pre); pre = fmaf(a0.y, dw0.y, pre);
            pre = fmaf(a0.z, dw0.z, pre); pre = fmaf(a0.w, dw0.w, pre);
            pre = fmaf(a1.x, dw1.x, pre); pre = fmaf(a1.y, dw1.y, pre);
            pre = fmaf(a1.z, dw1.z, pre); pre = fmaf(a1.w, dw1.w, pre);
            float dv = softplusf(pre);
            float u = pU[t * 256];
            float du = dv * u;
            const float* Bp = &pBC[t * 40 + 8];
            float ys = 0.0f;
#pragma unroll
            for (int s = 0; s < 16; s++) {
                float a = __expf(dv * As[s]);
                h[s] = fmaf(a, h[s], du * Bp[s]);
                ys = fmaf(h[s], Bp[16 + s], ys);
            }
            float z = siluf(pZ[t * 512]);
            pY[t * 256] = fmaf(u, Dreg, ys) * z;
        }
    }
}

// ---------------------------------------------------------------------------
// K6: out_proj GEMM  (YT token-major, kk-fast coalesced A load)
// ---------------------------------------------------------------------------
__global__ void k_gemm_out() {
    __shared__ float As[64][65];
    __shared__ float Ws[64][64];
    int nt = blockIdx.x;
    int tt = blockIdx.y;
    int ib = blockIdx.z;
    int i = ib >> 2;
    int T = scanT(i);
    if (tt * 64 >= T) return;
    int t0 = tt * 64;
    int SB = c_TB[ib];
    int tid = threadIdx.x;
    int tx = tid & 15, ty = tid >> 4;
    float acc[4][4] = {};
    for (int kc = 0; kc < 4; kc++) {
        for (int p = 0; p < 16; p++) {
            int idx = p * 256 + tid;
            int kk = idx & 63, m = idx >> 6;   // kk fast -> coalesced global read
            As[kk][m] = g_YT[(SB + t0 + m) * 256 + kc * 64 + kk];
        }
        for (int p = 0; p < 16; p++) {
            int idx = p * 256 + tid;
            int n = idx & 63, kk = idx >> 6;
            Ws[kk][n] = g_WTout[(i * 256 + kc * 64 + kk) * 128 + nt * 64 + n];
        }
        __syncthreads();
#pragma unroll
        for (int kk = 0; kk < 64; kk++) {
            float4 bv = *(const float4*)&Ws[kk][tx * 4];
            float av[4];
#pragma unroll
            for (int im = 0; im < 4; im++) av[im] = As[kk][ty * 4 + im];
#pragma unroll
            for (int im = 0; im < 4; im++) {
                acc[im][0] = fmaf(av[im], bv.x, acc[im][0]);
                acc[im][1] = fmaf(av[im], bv.y, acc[im][1]);
                acc[im][2] = fmaf(av[im], bv.z, acc[im][2]);
                acc[im][3] = fmaf(av[im], bv.w, acc[im][3]);
            }
        }
        __syncthreads();
    }
#pragma unroll
    for (int im = 0; im < 4; im++) {
        int t = t0 + ty * 4 + im;
        float4 v = make_float4(acc[im][0], acc[im][1], acc[im][2], acc[im][3]);
        *(float4*)&g_OUT[(SB + t) * 128 + nt * 64 + tx * 4] = v;
    }
}

// interp of backward-scan output (len 4096 -> index 8191-l of the len-8192 signal)
__device__ __forceinline__ float interp_flip(int i, int b, int l, int c) {
    float pos = 0.5f * (float)(8191 - l) - 0.25f;
    pos = fminf(fmaxf(pos, 0.0f), 4095.0f);
    int lo = (int)floorf(pos);
    int hi = min(lo + 1, 4095);
    float w = pos - (float)lo;
    const float* ob = &g_OUT[c_TB[i * 4 + b] * 128 + c];
    return ob[lo * 128] * (1.0f - w) + ob[hi * 128] * w;
}

// ---------------------------------------------------------------------------
// K7: merge 4 scan outputs -> a,b maps [2][B][C][64][64] (smem transpose)
// ---------------------------------------------------------------------------
__global__ void k_merge() {
    __shared__ float S[64][129];
    int irow = blockIdx.x;
    int b = blockIdx.y;
    int tid = threadIdx.x;
    for (int half = 0; half < 2; half++) {
        for (int p = 0; p < 32; p++) {
            int idx = p * 256 + tid;
            int c = idx & 127, j = idx >> 7;
            int l  = irow * 128 + j + (half ? 64 : 0);
            int l2 = j * 128 + irow + (half ? 64 : 0);
            float v = g_OUT[(c_TB[b] + l) * 128 + c];
            v += interp_flip(1, b, l, c);
            v += g_OUT[(c_TB[8 + b] + l2) * 128 + c];
            v += interp_flip(3, b, l2, c);
            S[j][c] = v;
        }
        __syncthreads();
        for (int p = 0; p < 32; p++) {
            int idx = p * 256 + tid;
            int j = idx & 63, c = idx >> 6;
            g_AB[((half * 4 + b) * 128 + c) * 4096 + irow * 64 + j] = S[j][c];
        }
        __syncthreads();
    }
}

// ---------------------------------------------------------------------------
// K8: bilinear 64->128 upsample of a and b, + feat_a + feat_b
// ---------------------------------------------------------------------------
__global__ void k_final(const float* __restrict__ fa, const float* __restrict__ fb,
                        float* __restrict__ out) {
    int idx = blockIdx.x * 256 + threadIdx.x;
    int w = idx & 127, hh = (idx >> 7) & 127, c = (idx >> 14) & 127, b = idx >> 21;
    float ph = fminf(fmaxf(0.5f * hh - 0.25f, 0.0f), 63.0f);
    int h0 = (int)floorf(ph); int h1 = min(h0 + 1, 63); float wh = ph - (float)h0;
    float pw = fminf(fmaxf(0.5f * w - 0.25f, 0.0f), 63.0f);
    int w0 = (int)floorf(pw); int w1 = min(w0 + 1, 63); float ww = pw - (float)w0;
    const float* Aa = &g_AB[((0 * 4 + b) * 128 + c) * 4096];
    const float* Bb = &g_AB[((1 * 4 + b) * 128 + c) * 4096];
    float av = (Aa[h0 * 64 + w0] * (1.0f - ww) + Aa[h0 * 64 + w1] * ww) * (1.0f - wh)
             + (Aa[h1 * 64 + w0] * (1.0f - ww) + Aa[h1 * 64 + w1] * ww) * wh;
    float bv = (Bb[h0 * 64 + w0] * (1.0f - ww) + Bb[h0 * 64 + w1] * ww) * (1.0f - wh)
             + (Bb[h1 * 64 + w0] * (1.0f - ww) + Bb[h1 * 64 + w1] * ww) * wh;
    out[idx] = av + bv + fa[idx] + fb[idx];
}

// ---------------------------------------------------------------------------
extern "C" void kernel_launch(void* const* d_in, const int* in_sizes, int n_in,
                              void* d_out, int out_size) {
    (void)in_sizes; (void)n_in; (void)out_size;
    const float* fa   = (const float*)d_in[0];
    const float* fb   = (const float*)d_in[1];
    const float* inw  = (const float*)d_in[2];
    const float* cw   = (const float*)d_in[3];
    const float* cb   = (const float*)d_in[4];
    const float* xpw  = (const float*)d_in[5];
    const float* dtw  = (const float*)d_in[6];
    const float* dtb  = (const float*)d_in[7];
    const float* alog = (const float*)d_in[8];
    const float* Dv   = (const float*)d_in[9];
    const float* outw = (const float*)d_in[10];
    float* out = (float*)d_out;

    k_reset<<<1, 1>>>();
    k_prep<<<1024, 256>>>(inw, xpw, outw, alog);
    k_gemm_in<<<dim3(8, 128, 16), 256>>>(fa, fb);
    k_conv<<<dim3(128, 16), 256>>>(cw, cb);
    k_gemm_xp<<<dim3(1, 128, 16), 256>>>();
    k_scan1<<<dim3(NCHUNK, 16), 256>>>(alog, dtw, dtb);
    k_scan2<<<256, 256>>>();
    k_scan3<<<dim3(NCHUNK, 16), 256>>>(alog, Dv, dtw, dtb);
    k_gemm_out<<<dim3(2, 128, 16), 256>>>();
    k_merge<<<dim3(64, 4), 256>>>();
    k_final<<<32768, 256>>>(fa, fb, out);
}

// round 7
// speedup vs baseline: 4.2786x; 1.2920x over previous
#include <cuda_runtime.h>
#include <math.h>
#include <stdint.h>

// ---------------------------------------------------------------------------
// JointMambaFusion: B=4, C=128, H=W=128, D_INNER=256, D_STATE=16, DT_RANK=8
// 4 scans: T = {8192, 4096, 8192, 4096}; token bases c_TB[ib], TOKTOT tokens.
// GEMMs on tf32 tensor cores (mma.sync.m16n8k8). Intermediates token-major.
// ---------------------------------------------------------------------------

#define TOKTOT 98304
#define NCHUNK 32

__constant__ int c_TB[16] = {
    0,     8192,  16384, 24576,
    32768, 36864, 40960, 45056,
    49152, 57344, 65536, 73728,
    81920, 86016, 90112, 94208
};

__device__ float g_XZ   [TOKTOT * 512];
__device__ float g_XS   [TOKTOT * 256];
__device__ float g_XDBL [TOKTOT * 40];
__device__ float g_YT   [TOKTOT * 256];
__device__ float g_OUT  [TOKTOT * 128];
__device__ float g_AB   [2 * 4 * 128 * 64 * 64];
__device__ float g_WTin [4 * 128 * 512];
__device__ float g_WTxp [4 * 256 * 64];
__device__ float g_WTout[4 * 256 * 128];
__device__ float g_CP [16 * NCHUNK * 256 * 16];
__device__ float g_CH [16 * NCHUNK * 256 * 16];
__device__ float g_HI [16 * NCHUNK * 256 * 16];
__device__ int   g_powBad;

__device__ __forceinline__ int scanT(int i) { return (i & 1) ? 4096 : 8192; }

__device__ __forceinline__ float siluf(float x) {
    return __fdividef(x, 1.0f + __expf(-x));
}
__device__ __forceinline__ float softplusf(float x) {
    return (x > 15.0f) ? x : __logf(1.0f + __expf(x));
}
__device__ __forceinline__ uint32_t tf32r(float x) {
    uint32_t u; asm("cvt.rna.tf32.f32 %0, %1;" : "=r"(u) : "f"(x)); return u;
}
__device__ __forceinline__ uint32_t fau(float x) { return __float_as_uint(x); }

#define MMA_TF32(C, A, B)                                                     \
    asm volatile("mma.sync.aligned.m16n8k8.row.col.f32.tf32.tf32.f32 "        \
        "{%0,%1,%2,%3},{%4,%5,%6,%7},{%8,%9},{%0,%1,%2,%3};"                  \
        : "+f"((C)[0]), "+f"((C)[1]), "+f"((C)[2]), "+f"((C)[3])              \
        : "r"((A)[0]), "r"((A)[1]), "r"((A)[2]), "r"((A)[3]),                 \
          "r"((B)[0]), "r"((B)[1]))

// scan-direction gather: x_i[b, t, c] from feat_a / feat_b
__device__ __forceinline__ float gather_x(int i, int b, int t, int c,
                                          const float* __restrict__ fa,
                                          const float* __restrict__ fb) {
    int l = (i & 1) ? (8191 - 2 * t) : t;
    int base = (b * 128 + c) * 128;
    if (i < 2) {
        int hh = l >> 7, ww = l & 127;
        if (ww < 64) return fa[(base + 2 * hh) * 128 + 2 * ww];
        else         return fb[(base + 2 * hh) * 128 + 2 * ww - 128];
    } else {
        int ww = l >> 7, rr = l & 127;
        if (rr < 64) return fa[(base + 2 * rr) * 128 + 2 * ww];
        else         return fb[(base + 2 * rr - 128) * 128 + 2 * ww];
    }
}

// ---------------------------------------------------------------------------
__global__ void k_reset() { g_powBad = 0; }

__global__ void k_prep(const float* __restrict__ inw,
                       const float* __restrict__ xpw,
                       const float* __restrict__ outw,
                       const float* __restrict__ alog) {
    int idx = blockIdx.x * 256 + threadIdx.x;
    if (idx < 4 * 512 * 128) {
        int i = idx / (512 * 128), r = idx % (512 * 128);
        int e = r / 128, c = r % 128;
        g_WTin[(i * 128 + c) * 512 + e] = inw[idx];
    }
    if (idx < 4 * 256 * 64) {
        int i = idx / (256 * 64), r = idx % (256 * 64);
        int c = r / 64, e = r % 64;
        g_WTxp[idx] = (e < 40) ? xpw[(i * 40 + e) * 256 + c] : 0.0f;
    }
    if (idx < 4 * 256 * 128) {
        int i = idx / (256 * 128), r = idx % (256 * 128);
        int c = r / 128, o = r % 128;
        g_WTout[idx] = outw[(i * 128 + o) * 256 + c];
    }
    if (idx < 4 * 256 * 16) {
        int s = idx & 15;
        int dI = idx >> 4;
        float As = -__expf(alog[dI * 16 + s]);
        float A0 = -__expf(alog[dI * 16]);
        float ratio = As / A0;
        if (fabsf(ratio - (float)(s + 1)) > 1e-5f * (float)(s + 1))
            atomicOr(&g_powBad, 1);
    }
}

// ---------------------------------------------------------------------------
// K1: in_proj tf32 GEMM.  tile 128x64, K=128, gather-fused A.
// ---------------------------------------------------------------------------
__global__ void k_gemm_in(const float* __restrict__ fa, const float* __restrict__ fb) {
    __shared__ __align__(16) float As[128][36];
    __shared__ __align__(16) float Bs[32][72];
    int nt = blockIdx.x;                 // 0..7
    int tt = blockIdx.y;
    int ib = blockIdx.z;
    int i = ib >> 2, b = ib & 3;
    int T = scanT(i);
    if (tt * 128 >= T) return;
    int t0 = tt * 128;
    int tid = threadIdx.x;
    int warp = tid >> 5, lane = tid & 31;
    int wm = warp & 3, wn = warp >> 2;
    int lg = lane >> 2, lt = lane & 3;
    float c[2][4][4] = {};
    for (int kc = 0; kc < 4; kc++) {
        for (int p = 0; p < 16; p++) {
            int idx = p * 256 + tid;
            int m = idx & 127, kk = idx >> 7;
            As[m][kk] = __uint_as_float(tf32r(gather_x(i, b, t0 + m, kc * 32 + kk, fa, fb)));
        }
        for (int p = 0; p < 2; p++) {
            int q = p * 256 + tid;
            int n4 = q & 15, kk = q >> 4;
            float4 v = *(const float4*)&g_WTin[(i * 128 + kc * 32 + kk) * 512 + nt * 64 + n4 * 4];
            float4 w = make_float4(__uint_as_float(tf32r(v.x)), __uint_as_float(tf32r(v.y)),
                                   __uint_as_float(tf32r(v.z)), __uint_as_float(tf32r(v.w)));
            *(float4*)&Bs[kk][n4 * 4] = w;
        }
        __syncthreads();
#pragma unroll
        for (int k8 = 0; k8 < 4; k8++) {
            int kq = k8 * 8 + lt;
            uint32_t a[2][4];
#pragma unroll
            for (int mt = 0; mt < 2; mt++) {
                int mr = wm * 32 + mt * 16 + lg;
                a[mt][0] = fau(As[mr][kq]);     a[mt][1] = fau(As[mr + 8][kq]);
                a[mt][2] = fau(As[mr][kq + 4]); a[mt][3] = fau(As[mr + 8][kq + 4]);
            }
            uint32_t bb[4][2];
#pragma unroll
            for (int n4 = 0; n4 < 4; n4++) {
                int nb = wn * 32 + n4 * 8 + lg;
                bb[n4][0] = fau(Bs[kq][nb]);
                bb[n4][1] = fau(Bs[kq + 4][nb]);
            }
#pragma unroll
            for (int mt = 0; mt < 2; mt++)
#pragma unroll
                for (int n4 = 0; n4 < 4; n4++)
                    MMA_TF32(c[mt][n4], a[mt], bb[n4]);
        }
        __syncthreads();
    }
    int SB = c_TB[ib];
#pragma unroll
    for (int mt = 0; mt < 2; mt++)
#pragma unroll
        for (int n4 = 0; n4 < 4; n4++) {
            int row = t0 + wm * 32 + mt * 16 + lg;
            int col = nt * 64 + wn * 32 + n4 * 8 + 2 * lt;
            *(float2*)&g_XZ[(SB + row) * 512 + col]     = make_float2(c[mt][n4][0], c[mt][n4][1]);
            *(float2*)&g_XZ[(SB + row + 8) * 512 + col] = make_float2(c[mt][n4][2], c[mt][n4][3]);
        }
}

// ---------------------------------------------------------------------------
// K2: causal conv(4)+silu -> XS token-major.
// ---------------------------------------------------------------------------
__global__ void k_conv(const float* __restrict__ cw, const float* __restrict__ cb) {
    int tc = blockIdx.x, ib = blockIdx.y;
    int i = ib >> 2;
    int T = scanT(i);
    if (tc * 64 >= T) return;
    int d = threadIdx.x;
    int SB = c_TB[ib];
    const float* w = &cw[(i * 256 + d) * 4];
    float w0 = w[0], w1 = w[1], w2 = w[2], w3 = w[3];
    float bias = cb[i * 256 + d];
    const float* px = &g_XZ[SB * 512 + d];
    float* pxs = &g_XS[SB * 256 + d];
    int t0 = tc * 64;
    float xm1 = (t0 >= 1) ? px[(t0 - 1) * 512] : 0.0f;
    float xm2 = (t0 >= 2) ? px[(t0 - 2) * 512] : 0.0f;
    float xm3 = (t0 >= 3) ? px[(t0 - 3) * 512] : 0.0f;
    for (int q4 = 0; q4 < 16; q4++) {
        float xv[4];
#pragma unroll
        for (int j = 0; j < 4; j++) xv[j] = px[(t0 + q4 * 4 + j) * 512];
#pragma unroll
        for (int j = 0; j < 4; j++) {
            float x = xv[j];
            float acc = fmaf(x, w3, fmaf(xm1, w2, fmaf(xm2, w1, fmaf(xm3, w0, bias))));
            pxs[(t0 + q4 * 4 + j) * 256] = siluf(acc);
            xm3 = xm2; xm2 = xm1; xm1 = x;
        }
    }
}

// ---------------------------------------------------------------------------
// K3: x_proj tf32 GEMM.  tile 128x64, K=256.  valid cols < 40.
// ---------------------------------------------------------------------------
__global__ void k_gemm_xp() {
    __shared__ __align__(16) float As[128][36];
    __shared__ __align__(16) float Bs[32][72];
    int tt = blockIdx.y;
    int ib = blockIdx.z;
    int i = ib >> 2;
    int T = scanT(i);
    if (tt * 128 >= T) return;
    int t0 = tt * 128;
    int SB = c_TB[ib];
    int tid = threadIdx.x;
    int warp = tid >> 5, lane = tid & 31;
    int wm = warp & 3, wn = warp >> 2;
    int lg = lane >> 2, lt = lane & 3;
    float c[2][4][4] = {};
    for (int kc = 0; kc < 8; kc++) {
        for (int p = 0; p < 4; p++) {
            int q = p * 256 + tid;
            int kk4 = q & 7, m = q >> 3;
            float4 v = *(const float4*)&g_XS[(SB + t0 + m) * 256 + kc * 32 + kk4 * 4];
            float4 w = make_float4(__uint_as_float(tf32r(v.x)), __uint_as_float(tf32r(v.y)),
                                   __uint_as_float(tf32r(v.z)), __uint_as_float(tf32r(v.w)));
            *(float4*)&As[m][kk4 * 4] = w;
        }
        for (int p = 0; p < 2; p++) {
            int q = p * 256 + tid;
            int n4 = q & 15, kk = q >> 4;
            float4 v = *(const float4*)&g_WTxp[(i * 256 + kc * 32 + kk) * 64 + n4 * 4];
            float4 w = make_float4(__uint_as_float(tf32r(v.x)), __uint_as_float(tf32r(v.y)),
                                   __uint_as_float(tf32r(v.z)), __uint_as_float(tf32r(v.w)));
            *(float4*)&Bs[kk][n4 * 4] = w;
        }
        __syncthreads();
#pragma unroll
        for (int k8 = 0; k8 < 4; k8++) {
            int kq = k8 * 8 + lt;
            uint32_t a[2][4];
#pragma unroll
            for (int mt = 0; mt < 2; mt++) {
                int mr = wm * 32 + mt * 16 + lg;
                a[mt][0] = fau(As[mr][kq]);     a[mt][1] = fau(As[mr + 8][kq]);
                a[mt][2] = fau(As[mr][kq + 4]); a[mt][3] = fau(As[mr + 8][kq + 4]);
            }
            uint32_t bb[4][2];
#pragma unroll
            for (int n4 = 0; n4 < 4; n4++) {
                int nb = wn * 32 + n4 * 8 + lg;
                bb[n4][0] = fau(Bs[kq][nb]);
                bb[n4][1] = fau(Bs[kq + 4][nb]);
            }
#pragma unroll
            for (int mt = 0; mt < 2; mt++)
#pragma unroll
                for (int n4 = 0; n4 < 4; n4++)
                    MMA_TF32(c[mt][n4], a[mt], bb[n4]);
        }
        __syncthreads();
    }
#pragma unroll
    for (int mt = 0; mt < 2; mt++)
#pragma unroll
        for (int n4 = 0; n4 < 4; n4++) {
            int row = t0 + wm * 32 + mt * 16 + lg;
            int col = wn * 32 + n4 * 8 + 2 * lt;
            if (col < 40) {
                *(float2*)&g_XDBL[(SB + row) * 40 + col]     = make_float2(c[mt][n4][0], c[mt][n4][1]);
                *(float2*)&g_XDBL[(SB + row + 8) * 40 + col] = make_float2(c[mt][n4][2], c[mt][n4][3]);
            }
        }
}

// ---------------------------------------------------------------------------
// K5a: chunk-local scan (delta fused inline). thread=d.
// ---------------------------------------------------------------------------
__global__ void k_scan1(const float* __restrict__ alog,
                        const float* __restrict__ dtw, const float* __restrict__ dtb) {
    int c = blockIdx.x, ib = blockIdx.y;
    int i = ib >> 2;
    int T = scanT(i);
    int LC = T / NCHUNK;
    int d = threadIdx.x;
    int SB = c_TB[ib];
    bool pw = (g_powBad == 0);
    float A0 = -__expf(alog[(i * 256 + d) * 16]);
    float4 dw0 = *(const float4*)&dtw[(i * 256 + d) * 8];
    float4 dw1 = *(const float4*)&dtw[(i * 256 + d) * 8 + 4];
    float dbias = dtb[i * 256 + d];
    const float* pU = &g_XS[SB * 256 + d];
    const float* pBC = &g_XDBL[SB * 40];
    float h[16];
#pragma unroll
    for (int s = 0; s < 16; s++) h[s] = 0.0f;
    float dsum = 0.0f;
    int t0 = c * LC;
    if (pw) {
#pragma unroll 2
        for (int t = t0; t < t0 + LC; t++) {
            const float4* r = (const float4*)&pBC[t * 40];
            float4 a0 = r[0], a1 = r[1];
            float pre = dbias;
            pre = fmaf(a0.x, dw0.x, pre); pre = fmaf(a0.y, dw0.y, pre);
            pre = fmaf(a0.z, dw0.z, pre); pre = fmaf(a0.w, dw0.w, pre);
            pre = fmaf(a1.x, dw1.x, pre); pre = fmaf(a1.y, dw1.y, pre);
            pre = fmaf(a1.z, dw1.z, pre); pre = fmaf(a1.w, dw1.w, pre);
            float dv = softplusf(pre);
            float du = dv * pU[t * 256];
            dsum += dv;
            float q = __expf(dv * A0);
            float4 B0 = r[2], B1 = r[3], B2 = r[4], B3 = r[5];
            float ap = q;
            h[0]  = fmaf(ap, h[0],  du * B0.x); ap *= q;
            h[1]  = fmaf(ap, h[1],  du * B0.y); ap *= q;
            h[2]  = fmaf(ap, h[2],  du * B0.z); ap *= q;
            h[3]  = fmaf(ap, h[3],  du * B0.w); ap *= q;
            h[4]  = fmaf(ap, h[4],  du * B1.x); ap *= q;
            h[5]  = fmaf(ap, h[5],  du * B1.y); ap *= q;
            h[6]  = fmaf(ap, h[6],  du * B1.z); ap *= q;
            h[7]  = fmaf(ap, h[7],  du * B1.w); ap *= q;
            h[8]  = fmaf(ap, h[8],  du * B2.x); ap *= q;
            h[9]  = fmaf(ap, h[9],  du * B2.y); ap *= q;
            h[10] = fmaf(ap, h[10], du * B2.z); ap *= q;
            h[11] = fmaf(ap, h[11], du * B2.w); ap *= q;
            h[12] = fmaf(ap, h[12], du * B3.x); ap *= q;
            h[13] = fmaf(ap, h[13], du * B3.y); ap *= q;
            h[14] = fmaf(ap, h[14], du * B3.z); ap *= q;
            h[15] = fmaf(ap, h[15], du * B3.w);
        }
    } else {
        float As[16];
#pragma unroll
        for (int s = 0; s < 16; s++) As[s] = -__expf(alog[(i * 256 + d) * 16 + s]);
        for (int t = t0; t < t0 + LC; t++) {
            const float4* r = (const float4*)&pBC[t * 40];
            float4 a0 = r[0], a1 = r[1];
            float pre = dbias;
            pre = fmaf(a0.x, dw0.x, pre); pre = fmaf(a0.y, dw0.y, pre);
            pre = fmaf(a0.z, dw0.z, pre); pre = fmaf(a0.w, dw0.w, pre);
            pre = fmaf(a1.x, dw1.x, pre); pre = fmaf(a1.y, dw1.y, pre);
            pre = fmaf(a1.z, dw1.z, pre); pre = fmaf(a1.w, dw1.w, pre);
            float dv = softplusf(pre);
            float du = dv * pU[t * 256];
            dsum += dv;
            const float* Bp = &pBC[t * 40 + 8];
#pragma unroll
            for (int s = 0; s < 16; s++) {
                float a = __expf(dv * As[s]);
                h[s] = fmaf(a, h[s], du * Bp[s]);
            }
        }
    }
    int base = ((ib * NCHUNK + c) * 256 + d) * 16;
#pragma unroll
    for (int s = 0; s < 16; s++) {
        float Ascale = pw ? (A0 * (float)(s + 1))
                          : (-__expf(alog[(i * 256 + d) * 16 + s]));
        g_CP[base + s] = __expf(Ascale * dsum);
        g_CH[base + s] = h[s];
    }
}

// ---------------------------------------------------------------------------
// K5b: prefix over chunks
// ---------------------------------------------------------------------------
__global__ void k_scan2() {
    int g = blockIdx.x * 256 + threadIdx.x;
    int ib = g >> 12;
    int rem = g & 4095;
    float hi = 0.0f;
    for (int c = 0; c < NCHUNK; c++) {
        int idx = ib * (NCHUNK * 4096) + c * 4096 + rem;
        g_HI[idx] = hi;
        hi = fmaf(g_CP[idx], hi, g_CH[idx]);
    }
}

// ---------------------------------------------------------------------------
// K5c: chunk recompute with true h_init; y -> YT token-major
// ---------------------------------------------------------------------------
__global__ void k_scan3(const float* __restrict__ alog, const float* __restrict__ Dv,
                        const float* __restrict__ dtw, const float* __restrict__ dtb) {
    int c = blockIdx.x, ib = blockIdx.y;
    int i = ib >> 2;
    int T = scanT(i);
    int LC = T / NCHUNK;
    int d = threadIdx.x;
    int SB = c_TB[ib];
    bool pw = (g_powBad == 0);
    float A0 = -__expf(alog[(i * 256 + d) * 16]);
    float Dreg = Dv[i * 256 + d];
    float4 dw0 = *(const float4*)&dtw[(i * 256 + d) * 8];
    float4 dw1 = *(const float4*)&dtw[(i * 256 + d) * 8 + 4];
    float dbias = dtb[i * 256 + d];
    const float* pU = &g_XS[SB * 256 + d];
    const float* pZ = &g_XZ[SB * 512 + 256 + d];
    const float* pBC = &g_XDBL[SB * 40];
    float* pY = &g_YT[SB * 256 + d];
    float h[16];
    {
        int base = ((ib * NCHUNK + c) * 256 + d) * 16;
#pragma unroll
        for (int s = 0; s < 16; s++) h[s] = g_HI[base + s];
    }
    int t0 = c * LC;
    if (pw) {
#pragma unroll 2
        for (int t = t0; t < t0 + LC; t++) {
            const float4* r = (const float4*)&pBC[t * 40];
            float4 a0 = r[0], a1 = r[1];
            float pre = dbias;
            pre = fmaf(a0.x, dw0.x, pre); pre = fmaf(a0.y, dw0.y, pre);
            pre = fmaf(a0.z, dw0.z, pre); pre = fmaf(a0.w, dw0.w, pre);
            pre = fmaf(a1.x, dw1.x, pre); pre = fmaf(a1.y, dw1.y, pre);
            pre = fmaf(a1.z, dw1.z, pre); pre = fmaf(a1.w, dw1.w, pre);
            float dv = softplusf(pre);
            float u = pU[t * 256];
            float du = dv * u;
            float q = __expf(dv * A0);
            float4 B0 = r[2], B1 = r[3], B2 = r[4], B3 = r[5];
            float4 C0 = r[6], C1 = r[7], C2 = r[8], C3 = r[9];
            float ys = 0.0f;
            float ap = q;
            h[0]  = fmaf(ap, h[0],  du * B0.x); ys = fmaf(h[0],  C0.x, ys); ap *= q;
            h[1]  = fmaf(ap, h[1],  du * B0.y); ys = fmaf(h[1],  C0.y, ys); ap *= q;
            h[2]  = fmaf(ap, h[2],  du * B0.z); ys = fmaf(h[2],  C0.z, ys); ap *= q;
            h[3]  = fmaf(ap, h[3],  du * B0.w); ys = fmaf(h[3],  C0.w, ys); ap *= q;
            h[4]  = fmaf(ap, h[4],  du * B1.x); ys = fmaf(h[4],  C1.x, ys); ap *= q;
            h[5]  = fmaf(ap, h[5],  du * B1.y); ys = fmaf(h[5],  C1.y, ys); ap *= q;
            h[6]  = fmaf(ap, h[6],  du * B1.z); ys = fmaf(h[6],  C1.z, ys); ap *= q;
            h[7]  = fmaf(ap, h[7],  du * B1.w); ys = fmaf(h[7],  C1.w, ys); ap *= q;
            h[8]  = fmaf(ap, h[8],  du * B2.x); ys = fmaf(h[8],  C2.x, ys); ap *= q;
            h[9]  = fmaf(ap, h[9],  du * B2.y); ys = fmaf(h[9],  C2.y, ys); ap *= q;
            h[10] = fmaf(ap, h[10], du * B2.z); ys = fmaf(h[10], C2.z, ys); ap *= q;
            h[11] = fmaf(ap, h[11], du * B2.w); ys = fmaf(h[11], C2.w, ys); ap *= q;
            h[12] = fmaf(ap, h[12], du * B3.x); ys = fmaf(h[12], C3.x, ys); ap *= q;
            h[13] = fmaf(ap, h[13], du * B3.y); ys = fmaf(h[13], C3.y, ys); ap *= q;
            h[14] = fmaf(ap, h[14], du * B3.z); ys = fmaf(h[14], C3.z, ys); ap *= q;
            h[15] = fmaf(ap, h[15], du * B3.w); ys = fmaf(h[15], C3.w, ys);
            float z = siluf(pZ[t * 512]);
            pY[t * 256] = fmaf(u, Dreg, ys) * z;
        }
    } else {
        float As[16];
#pragma unroll
        for (int s = 0; s < 16; s++) As[s] = -__expf(alog[(i * 256 + d) * 16 + s]);
        for (int t = t0; t < t0 + LC; t++) {
            const float4* r = (const float4*)&pBC[t * 40];
            float4 a0 = r[0], a1 = r[1];
            float pre = dbias;
            pre = fmaf(a0.x, dw0.x, pre); pre = fmaf(a0.y, dw0.y, pre);
            pre = fmaf(a0.z, dw0.z, pre); pre = fmaf(a0.w, dw0.w, pre);
            pre = fmaf(a1.x, dw1.x, pre); pre = fmaf(a1.y, dw1.y, pre);
            pre = fmaf(a1.z, dw1.z, pre); pre = fmaf(a1.w, dw1.w, pre);
            float dv = softplusf(pre);
            float u = pU[t * 256];
            float du = dv * u;
            const float* Bp = &pBC[t * 40 + 8];
            float ys = 0.0f;
#pragma unroll
            for (int s = 0; s < 16; s++) {
                float a = __expf(dv * As[s]);
                h[s] = fmaf(a, h[s], du * Bp[s]);
                ys = fmaf(h[s], Bp[16 + s], ys);
            }
            float z = siluf(pZ[t * 512]);
            pY[t * 256] = fmaf(u, Dreg, ys) * z;
        }
    }
}

// ---------------------------------------------------------------------------
// K6: out_proj tf32 GEMM.  tile 128x64, K=256, nt in {0,1}.
// ---------------------------------------------------------------------------
__global__ void k_gemm_out() {
    __shared__ __align__(16) float As[128][36];
    __shared__ __align__(16) float Bs[32][72];
    int nt = blockIdx.x;
    int tt = blockIdx.y;
    int ib = blockIdx.z;
    int i = ib >> 2;
    int T = scanT(i);
    if (tt * 128 >= T) return;
    int t0 = tt * 128;
    int SB = c_TB[ib];
    int tid = threadIdx.x;
    int warp = tid >> 5, lane = tid & 31;
    int wm = warp & 3, wn = warp >> 2;
    int lg = lane >> 2, lt = lane & 3;
    float c[2][4][4] = {};
    for (int kc = 0; kc < 8; kc++) {
        for (int p = 0; p < 4; p++) {
            int q = p * 256 + tid;
            int kk4 = q & 7, m = q >> 3;
            float4 v = *(const float4*)&g_YT[(SB + t0 + m) * 256 + kc * 32 + kk4 * 4];
            float4 w = make_float4(__uint_as_float(tf32r(v.x)), __uint_as_float(tf32r(v.y)),
                                   __uint_as_float(tf32r(v.z)), __uint_as_float(tf32r(v.w)));
            *(float4*)&As[m][kk4 * 4] = w;
        }
        for (int p = 0; p < 2; p++) {
            int q = p * 256 + tid;
            int n4 = q & 15, kk = q >> 4;
            float4 v = *(const float4*)&g_WTout[(i * 256 + kc * 32 + kk) * 128 + nt * 64 + n4 * 4];
            float4 w = make_float4(__uint_as_float(tf32r(v.x)), __uint_as_float(tf32r(v.y)),
                                   __uint_as_float(tf32r(v.z)), __uint_as_float(tf32r(v.w)));
            *(float4*)&Bs[kk][n4 * 4] = w;
        }
        __syncthreads();
#pragma unroll
        for (int k8 = 0; k8 < 4; k8++) {
            int kq = k8 * 8 + lt;
            uint32_t a[2][4];
#pragma unroll
            for (int mt = 0; mt < 2; mt++) {
                int mr = wm * 32 + mt * 16 + lg;
                a[mt][0] = fau(As[mr][kq]);     a[mt][1] = fau(As[mr + 8][kq]);
                a[mt][2] = fau(As[mr][kq + 4]); a[mt][3] = fau(As[mr + 8][kq + 4]);
            }
            uint32_t bb[4][2];
#pragma unroll
            for (int n4 = 0; n4 < 4; n4++) {
                int nb = wn * 32 + n4 * 8 + lg;
                bb[n4][0] = fau(Bs[kq][nb]);
                bb[n4][1] = fau(Bs[kq + 4][nb]);
            }
#pragma unroll
            for (int mt = 0; mt < 2; mt++)
#pragma unroll
                for (int n4 = 0; n4 < 4; n4++)
                    MMA_TF32(c[mt][n4], a[mt], bb[n4]);
        }
        __syncthreads();
    }
#pragma unroll
    for (int mt = 0; mt < 2; mt++)
#pragma unroll
        for (int n4 = 0; n4 < 4; n4++) {
            int row = t0 + wm * 32 + mt * 16 + lg;
            int col = nt * 64 + wn * 32 + n4 * 8 + 2 * lt;
            *(float2*)&g_OUT[(SB + row) * 128 + col]     = make_float2(c[mt][n4][0], c[mt][n4][1]);
            *(float2*)&g_OUT[(SB + row + 8) * 128 + col] = make_float2(c[mt][n4][2], c[mt][n4][3]);
        }
}

// interp of backward-scan output
__device__ __forceinline__ float interp_flip(int i, int b, int l, int c) {
    float pos = 0.5f * (float)(8191 - l) - 0.25f;
    pos = fminf(fmaxf(pos, 0.0f), 4095.0f);
    int lo = (int)floorf(pos);
    int hi = min(lo + 1, 4095);
    float w = pos - (float)lo;
    const float* ob = &g_OUT[c_TB[i * 4 + b] * 128 + c];
    return ob[lo * 128] * (1.0f - w) + ob[hi * 128] * w;
}

// ---------------------------------------------------------------------------
// K7: merge 4 scan outputs -> a,b maps [2][B][C][64][64]
// ---------------------------------------------------------------------------
__global__ void k_merge() {
    __shared__ float S[64][129];
    int irow = blockIdx.x;
    int b = blockIdx.y;
    int tid = threadIdx.x;
    for (int half = 0; half < 2; half++) {
        for (int p = 0; p < 32; p++) {
            int idx = p * 256 + tid;
            int c = idx & 127, j = idx >> 7;
            int l  = irow * 128 + j + (half ? 64 : 0);
            int l2 = j * 128 + irow + (half ? 64 : 0);
            float v = g_OUT[(c_TB[b] + l) * 128 + c];
            v += interp_flip(1, b, l, c);
            v += g_OUT[(c_TB[8 + b] + l2) * 128 + c];
            v += interp_flip(3, b, l2, c);
            S[j][c] = v;
        }
        __syncthreads();
        for (int p = 0; p < 32; p++) {
            int idx = p * 256 + tid;
            int j = idx & 63, c = idx >> 6;
            g_AB[((half * 4 + b) * 128 + c) * 4096 + irow * 64 + j] = S[j][c];
        }
        __syncthreads();
    }
}

// ---------------------------------------------------------------------------
// K8: bilinear 64->128 upsample + residuals
// ---------------------------------------------------------------------------
__global__ void k_final(const float* __restrict__ fa, const float* __restrict__ fb,
                        float* __restrict__ out) {
    int idx = blockIdx.x * 256 + threadIdx.x;
    int w = idx & 127, hh = (idx >> 7) & 127, c = (idx >> 14) & 127, b = idx >> 21;
    float ph = fminf(fmaxf(0.5f * hh - 0.25f, 0.0f), 63.0f);
    int h0 = (int)floorf(ph); int h1 = min(h0 + 1, 63); float wh = ph - (float)h0;
    float pw = fminf(fmaxf(0.5f * w - 0.25f, 0.0f), 63.0f);
    int w0 = (int)floorf(pw); int w1 = min(w0 + 1, 63); float ww = pw - (float)w0;
    const float* Aa = &g_AB[((0 * 4 + b) * 128 + c) * 4096];
    const float* Bb = &g_AB[((1 * 4 + b) * 128 + c) * 4096];
    float av = (Aa[h0 * 64 + w0] * (1.0f - ww) + Aa[h0 * 64 + w1] * ww) * (1.0f - wh)
             + (Aa[h1 * 64 + w0] * (1.0f - ww) + Aa[h1 * 64 + w1] * ww) * wh;
    float bv = (Bb[h0 * 64 + w0] * (1.0f - ww) + Bb[h0 * 64 + w1] * ww) * (1.0f - wh)
             + (Bb[h1 * 64 + w0] * (1.0f - ww) + Bb[h1 * 64 + w1] * ww) * wh;
    out[idx] = av + bv + fa[idx] + fb[idx];
}

// ---------------------------------------------------------------------------
extern "C" void kernel_launch(void* const* d_in, const int* in_sizes, int n_in,
                              void* d_out, int out_size) {
    (void)in_sizes; (void)n_in; (void)out_size;
    const float* fa   = (const float*)d_in[0];
    const float* fb   = (const float*)d_in[1];
    const float* inw  = (const float*)d_in[2];
    const float* cw   = (const float*)d_in[3];
    const float* cb   = (const float*)d_in[4];
    const float* xpw  = (const float*)d_in[5];
    const float* dtw  = (const float*)d_in[6];
    const float* dtb  = (const float*)d_in[7];
    const float* alog = (const float*)d_in[8];
    const float* Dv   = (const float*)d_in[9];
    const float* outw = (const float*)d_in[10];
    float* out = (float*)d_out;

    k_reset<<<1, 1>>>();
    k_prep<<<1024, 256>>>(inw, xpw, outw, alog);
    k_gemm_in<<<dim3(8, 64, 16), 256>>>(fa, fb);
    k_conv<<<dim3(128, 16), 256>>>(cw, cb);
    k_gemm_xp<<<dim3(1, 64, 16), 256>>>();
    k_scan1<<<dim3(NCHUNK, 16), 256>>>(alog, dtw, dtb);
    k_scan2<<<256, 256>>>();
    k_scan3<<<dim3(NCHUNK, 16), 256>>>(alog, Dv, dtw, dtb);
    k_gemm_out<<<dim3(2, 64, 16), 256>>>();
    k_merge<<<dim3(64, 4), 256>>>();
    k_final<<<32768, 256>>>(fa, fb, out);
}

// round 8
// speedup vs baseline: 5.7424x; 1.3421x over previous
#include <cuda_runtime.h>
#include <math.h>
#include <stdint.h>

// ---------------------------------------------------------------------------
// JointMambaFusion: B=4, C=128, H=W=128, D_INNER=256, D_STATE=16, DT_RANK=8
// 4 scans: T = {8192, 4096, 8192, 4096}; token bases c_TB[ib], TOKTOT tokens.
// GEMMs on tf32 tensor cores. X gathered ONCE into X_h; all scans are row
// permutations of X_h (vertical = transpose permutation of horizontal).
// ---------------------------------------------------------------------------

#define TOKTOT 98304
#define NCHUNK 32

__constant__ int c_TB[16] = {
    0,     8192,  16384, 24576,
    32768, 36864, 40960, 45056,
    49152, 57344, 65536, 73728,
    81920, 86016, 90112, 94208
};

__device__ float g_X    [4 * 8192 * 128];   // gathered h-scan layout per batch
__device__ float g_XZ   [TOKTOT * 512];     // xl | silu(z)
__device__ float g_XS   [TOKTOT * 256];
__device__ float g_XDBL [TOKTOT * 40];
__device__ float g_YT   [TOKTOT * 256];
__device__ float g_OUT  [TOKTOT * 128];
__device__ float g_AB   [2 * 4 * 128 * 64 * 64];
__device__ float g_WTin [4 * 128 * 512];
__device__ float g_WTxp [4 * 256 * 64];
__device__ float g_WTout[4 * 256 * 128];
__device__ float g_CP [16 * NCHUNK * 256 * 16];
__device__ float g_CH [16 * NCHUNK * 256 * 16];
__device__ float g_HI [16 * NCHUNK * 256 * 16];
__device__ int   g_powBad = 0;   // monotone 0->1; both paths correct

__device__ __forceinline__ int scanT(int i) { return (i & 1) ? 4096 : 8192; }

__device__ __forceinline__ float siluf(float x) {
    return __fdividef(x, 1.0f + __expf(-x));
}
__device__ __forceinline__ float softplusf(float x) {
    return (x > 15.0f) ? x : __logf(1.0f + __expf(x));
}
__device__ __forceinline__ uint32_t tf32r(float x) {
    uint32_t u; asm("cvt.rna.tf32.f32 %0, %1;" : "=r"(u) : "f"(x)); return u;
}
__device__ __forceinline__ uint32_t fau(float x) { return __float_as_uint(x); }
__device__ __forceinline__ float tf(float x) { return __uint_as_float(tf32r(x)); }

#define MMA_TF32(C, A, B)                                                     \
    asm volatile("mma.sync.aligned.m16n8k8.row.col.f32.tf32.tf32.f32 "        \
        "{%0,%1,%2,%3},{%4,%5,%6,%7},{%8,%9},{%0,%1,%2,%3};"                  \
        : "+f"((C)[0]), "+f"((C)[1]), "+f"((C)[2]), "+f"((C)[3])              \
        : "r"((A)[0]), "r"((A)[1]), "r"((A)[2]), "r"((A)[3]),                 \
          "r"((B)[0]), "r"((B)[1]))

// row in X_h for (scan i, token t)
__device__ __forceinline__ int rowmap(int i, int t) {
    if (i == 0) return t;
    if (i == 1) return 8191 - 2 * t;
    int l = (i == 2) ? t : (8191 - 2 * t);
    int ww = l >> 7, rr = l & 127;
    return (rr < 64) ? rr * 128 + ww : (rr - 64) * 128 + ww + 64;
}

// ---------------------------------------------------------------------------
// K-1: gather h-scan layout X_h[b][t=hh*128+ww][c] once (smem transpose)
// ---------------------------------------------------------------------------
__global__ void k_gather(const float* __restrict__ fa, const float* __restrict__ fb) {
    __shared__ float S[64][129];
    int half = blockIdx.x;               // 0..1 (ww 0-63 / 64-127)
    int hh = blockIdx.y;                 // 0..63
    int b = blockIdx.z;
    int tid = threadIdx.x;
    int warp = tid >> 5, lane = tid & 31;
    for (int j = 0; j < 16; j++) {
        int c = warp * 16 + j;
        int planebase = (b * 128 + c) * 16384 + 2 * hh * 128;
        for (int it = 0; it < 2; it++) {
            int wl = it * 32 + lane;     // 0..63 local
            int ww = half * 64 + wl;
            float v = (ww < 64) ? fa[planebase + 2 * ww]
                                : fb[planebase + 2 * ww - 128];
            S[wl][c] = v;
        }
    }
    __syncthreads();
    int base = (b * 8192 + hh * 128 + half * 64) * 128;
    for (int q = 0; q < 32; q++) {
        int idx = q * 256 + tid;
        int c = idx & 127, row = idx >> 7;
        g_X[base + row * 128 + c] = S[row][c];
    }
}

// ---------------------------------------------------------------------------
// K0a: weight transposes
// ---------------------------------------------------------------------------
__global__ void k_prep_w(const float* __restrict__ inw,
                         const float* __restrict__ xpw,
                         const float* __restrict__ outw) {
    int idx = blockIdx.x * 256 + threadIdx.x;
    if (idx < 4 * 512 * 128) {
        int i = idx / (512 * 128), r = idx % (512 * 128);
        int e = r / 128, c = r % 128;
        g_WTin[(i * 128 + c) * 512 + e] = inw[idx];
    }
    if (idx < 4 * 256 * 64) {
        int i = idx / (256 * 64), r = idx % (256 * 64);
        int c = r / 64, e = r % 64;
        g_WTxp[idx] = (e < 40) ? xpw[(i * 40 + e) * 256 + c] : 0.0f;
    }
    if (idx < 4 * 256 * 128) {
        int i = idx / (256 * 128), r = idx % (256 * 128);
        int c = r / 128, o = r % 128;
        g_WTout[idx] = outw[(i * 128 + o) * 256 + c];
    }
}

// K0b: A_log structure check
__global__ void k_prep_chk(const float* __restrict__ alog) {
    int idx = blockIdx.x * 256 + threadIdx.x;
    if (idx < 4 * 256 * 16) {
        int s = idx & 15;
        int dI = idx >> 4;
        float As = -__expf(alog[dI * 16 + s]);
        float A0 = -__expf(alog[dI * 16]);
        float ratio = As / A0;
        if (fabsf(ratio - (float)(s + 1)) > 1e-5f * (float)(s + 1))
            atomicOr(&g_powBad, 1);
    }
}

// ---------------------------------------------------------------------------
// K1: in_proj tf32 GEMM.  tile 128x64, K=128.  A rows = coalesced X_h rows.
// z half (nt>=4) gets silu applied in epilogue.
// ---------------------------------------------------------------------------
__global__ void k_gemm_in() {
    __shared__ __align__(16) float As[128][36];
    __shared__ __align__(16) float Bs[32][72];
    int nt = blockIdx.x;                 // 0..7
    int tt = blockIdx.y;
    int ib = blockIdx.z;
    int i = ib >> 2, b = ib & 3;
    int T = scanT(i);
    if (tt * 128 >= T) return;
    int t0 = tt * 128;
    int tid = threadIdx.x;
    int warp = tid >> 5, lane = tid & 31;
    int wm = warp & 3, wn = warp >> 2;
    int lg = lane >> 2, lt = lane & 3;
    float c[2][4][4] = {};
    for (int kc = 0; kc < 4; kc++) {
        for (int p = 0; p < 4; p++) {
            int q = p * 256 + tid;
            int kk4 = q & 7, m = q >> 3;
            int r = rowmap(i, t0 + m);
            float4 v = *(const float4*)&g_X[(b * 8192 + r) * 128 + kc * 32 + kk4 * 4];
            float4 w = make_float4(tf(v.x), tf(v.y), tf(v.z), tf(v.w));
            *(float4*)&As[m][kk4 * 4] = w;
        }
        for (int p = 0; p < 2; p++) {
            int q = p * 256 + tid;
            int n4 = q & 15, kk = q >> 4;
            float4 v = *(const float4*)&g_WTin[(i * 128 + kc * 32 + kk) * 512 + nt * 64 + n4 * 4];
            float4 w = make_float4(tf(v.x), tf(v.y), tf(v.z), tf(v.w));
            *(float4*)&Bs[kk][n4 * 4] = w;
        }
        __syncthreads();
#pragma unroll
        for (int k8 = 0; k8 < 4; k8++) {
            int kq = k8 * 8 + lt;
            uint32_t a[2][4];
#pragma unroll
            for (int mt = 0; mt < 2; mt++) {
                int mr = wm * 32 + mt * 16 + lg;
                a[mt][0] = fau(As[mr][kq]);     a[mt][1] = fau(As[mr + 8][kq]);
                a[mt][2] = fau(As[mr][kq + 4]); a[mt][3] = fau(As[mr + 8][kq + 4]);
            }
            uint32_t bb[4][2];
#pragma unroll
            for (int n4 = 0; n4 < 4; n4++) {
                int nb = wn * 32 + n4 * 8 + lg;
                bb[n4][0] = fau(Bs[kq][nb]);
                bb[n4][1] = fau(Bs[kq + 4][nb]);
            }
#pragma unroll
            for (int mt = 0; mt < 2; mt++)
#pragma unroll
                for (int n4 = 0; n4 < 4; n4++)
                    MMA_TF32(c[mt][n4], a[mt], bb[n4]);
        }
        __syncthreads();
    }
    int SB = c_TB[ib];
    bool isz = (nt >= 4);
#pragma unroll
    for (int mt = 0; mt < 2; mt++)
#pragma unroll
        for (int n4 = 0; n4 < 4; n4++) {
            int row = t0 + wm * 32 + mt * 16 + lg;
            int col = nt * 64 + wn * 32 + n4 * 8 + 2 * lt;
            float2 v0 = make_float2(c[mt][n4][0], c[mt][n4][1]);
            float2 v1 = make_float2(c[mt][n4][2], c[mt][n4][3]);
            if (isz) {
                v0.x = siluf(v0.x); v0.y = siluf(v0.y);
                v1.x = siluf(v1.x); v1.y = siluf(v1.y);
            }
            *(float2*)&g_XZ[(SB + row) * 512 + col]     = v0;
            *(float2*)&g_XZ[(SB + row + 8) * 512 + col] = v1;
        }
}

// ---------------------------------------------------------------------------
// K2: causal conv(4)+silu -> XS token-major.
// ---------------------------------------------------------------------------
__global__ void k_conv(const float* __restrict__ cw, const float* __restrict__ cb) {
    int tc = blockIdx.x, ib = blockIdx.y;
    int i = ib >> 2;
    int T = scanT(i);
    if (tc * 64 >= T) return;
    int d = threadIdx.x;
    int SB = c_TB[ib];
    const float* w = &cw[(i * 256 + d) * 4];
    float w0 = w[0], w1 = w[1], w2 = w[2], w3 = w[3];
    float bias = cb[i * 256 + d];
    const float* px = &g_XZ[SB * 512 + d];
    float* pxs = &g_XS[SB * 256 + d];
    int t0 = tc * 64;
    float xm1 = (t0 >= 1) ? px[(t0 - 1) * 512] : 0.0f;
    float xm2 = (t0 >= 2) ? px[(t0 - 2) * 512] : 0.0f;
    float xm3 = (t0 >= 3) ? px[(t0 - 3) * 512] : 0.0f;
    for (int q4 = 0; q4 < 16; q4++) {
        float xv[4];
#pragma unroll
        for (int j = 0; j < 4; j++) xv[j] = px[(t0 + q4 * 4 + j) * 512];
#pragma unroll
        for (int j = 0; j < 4; j++) {
            float x = xv[j];
            float acc = fmaf(x, w3, fmaf(xm1, w2, fmaf(xm2, w1, fmaf(xm3, w0, bias))));
            pxs[(t0 + q4 * 4 + j) * 256] = siluf(acc);
            xm3 = xm2; xm2 = xm1; xm1 = x;
        }
    }
}

// ---------------------------------------------------------------------------
// K3: x_proj tf32 GEMM.  tile 128x64, K=256.  valid cols < 40.
// ---------------------------------------------------------------------------
__global__ void k_gemm_xp() {
    __shared__ __align__(16) float As[128][36];
    __shared__ __align__(16) float Bs[32][72];
    int tt = blockIdx.y;
    int ib = blockIdx.z;
    int i = ib >> 2;
    int T = scanT(i);
    if (tt * 128 >= T) return;
    int t0 = tt * 128;
    int SB = c_TB[ib];
    int tid = threadIdx.x;
    int warp = tid >> 5, lane = tid & 31;
    int wm = warp & 3, wn = warp >> 2;
    int lg = lane >> 2, lt = lane & 3;
    float c[2][4][4] = {};
    for (int kc = 0; kc < 8; kc++) {
        for (int p = 0; p < 4; p++) {
            int q = p * 256 + tid;
            int kk4 = q & 7, m = q >> 3;
            float4 v = *(const float4*)&g_XS[(SB + t0 + m) * 256 + kc * 32 + kk4 * 4];
            float4 w = make_float4(tf(v.x), tf(v.y), tf(v.z), tf(v.w));
            *(float4*)&As[m][kk4 * 4] = w;
        }
        for (int p = 0; p < 2; p++) {
            int q = p * 256 + tid;
            int n4 = q & 15, kk = q >> 4;
            float4 v = *(const float4*)&g_WTxp[(i * 256 + kc * 32 + kk) * 64 + n4 * 4];
            float4 w = make_float4(tf(v.x), tf(v.y), tf(v.z), tf(v.w));
            *(float4*)&Bs[kk][n4 * 4] = w;
        }
        __syncthreads();
#pragma unroll
        for (int k8 = 0; k8 < 4; k8++) {
            int kq = k8 * 8 + lt;
            uint32_t a[2][4];
#pragma unroll
            for (int mt = 0; mt < 2; mt++) {
                int mr = wm * 32 + mt * 16 + lg;
                a[mt][0] = fau(As[mr][kq]);     a[mt][1] = fau(As[mr + 8][kq]);
                a[mt][2] = fau(As[mr][kq + 4]); a[mt][3] = fau(As[mr + 8][kq + 4]);
            }
            uint32_t bb[4][2];
#pragma unroll
            for (int n4 = 0; n4 < 4; n4++) {
                int nb = wn * 32 + n4 * 8 + lg;
                bb[n4][0] = fau(Bs[kq][nb]);
                bb[n4][1] = fau(Bs[kq + 4][nb]);
            }
#pragma unroll
            for (int mt = 0; mt < 2; mt++)
#pragma unroll
                for (int n4 = 0; n4 < 4; n4++)
                    MMA_TF32(c[mt][n4], a[mt], bb[n4]);
        }
        __syncthreads();
    }
#pragma unroll
    for (int mt = 0; mt < 2; mt++)
#pragma unroll
        for (int n4 = 0; n4 < 4; n4++) {
            int row = t0 + wm * 32 + mt * 16 + lg;
            int col = wn * 32 + n4 * 8 + 2 * lt;
            if (col < 40) {
                *(float2*)&g_XDBL[(SB + row) * 40 + col]     = make_float2(c[mt][n4][0], c[mt][n4][1]);
                *(float2*)&g_XDBL[(SB + row + 8) * 40 + col] = make_float2(c[mt][n4][2], c[mt][n4][3]);
            }
        }
}

// ---------------------------------------------------------------------------
// K5a: chunk-local scan (delta fused inline). thread=d.
// ---------------------------------------------------------------------------
__global__ void k_scan1(const float* __restrict__ alog,
                        const float* __restrict__ dtw, const float* __restrict__ dtb) {
    int c = blockIdx.x, ib = blockIdx.y;
    int i = ib >> 2;
    int T = scanT(i);
    int LC = T / NCHUNK;
    int d = threadIdx.x;
    int SB = c_TB[ib];
    bool pw = (g_powBad == 0);
    float A0 = -__expf(alog[(i * 256 + d) * 16]);
    float4 dw0 = *(const float4*)&dtw[(i * 256 + d) * 8];
    float4 dw1 = *(const float4*)&dtw[(i * 256 + d) * 8 + 4];
    float dbias = dtb[i * 256 + d];
    const float* pU = &g_XS[SB * 256 + d];
    const float* pBC = &g_XDBL[SB * 40];
    float h[16];
#pragma unroll
    for (int s = 0; s < 16; s++) h[s] = 0.0f;
    float dsum = 0.0f;
    int t0 = c * LC;
    if (pw) {
#pragma unroll 2
        for (int t = t0; t < t0 + LC; t++) {
            const float4* r = (const float4*)&pBC[t * 40];
            float4 a0 = r[0], a1 = r[1];
            float pre = dbias;
            pre = fmaf(a0.x, dw0.x, pre); pre = fmaf(a0.y, dw0.y, pre);
            pre = fmaf(a0.z, dw0.z, pre); pre = fmaf(a0.w, dw0.w, pre);
            pre = fmaf(a1.x, dw1.x, pre); pre = fmaf(a1.y, dw1.y, pre);
            pre = fmaf(a1.z, dw1.z, pre); pre = fmaf(a1.w, dw1.w, pre);
            float dv = softplusf(pre);
            float du = dv * pU[t * 256];
            dsum += dv;
            float q = __expf(dv * A0);
            float4 B0 = r[2], B1 = r[3], B2 = r[4], B3 = r[5];
            float ap = q;
            h[0]  = fmaf(ap, h[0],  du * B0.x); ap *= q;
            h[1]  = fmaf(ap, h[1],  du * B0.y); ap *= q;
            h[2]  = fmaf(ap, h[2],  du * B0.z); ap *= q;
            h[3]  = fmaf(ap, h[3],  du * B0.w); ap *= q;
            h[4]  = fmaf(ap, h[4],  du * B1.x); ap *= q;
            h[5]  = fmaf(ap, h[5],  du * B1.y); ap *= q;
            h[6]  = fmaf(ap, h[6],  du * B1.z); ap *= q;
            h[7]  = fmaf(ap, h[7],  du * B1.w); ap *= q;
            h[8]  = fmaf(ap, h[8],  du * B2.x); ap *= q;
            h[9]  = fmaf(ap, h[9],  du * B2.y); ap *= q;
            h[10] = fmaf(ap, h[10], du * B2.z); ap *= q;
            h[11] = fmaf(ap, h[11], du * B2.w); ap *= q;
            h[12] = fmaf(ap, h[12], du * B3.x); ap *= q;
            h[13] = fmaf(ap, h[13], du * B3.y); ap *= q;
            h[14] = fmaf(ap, h[14], du * B3.z); ap *= q;
            h[15] = fmaf(ap, h[15], du * B3.w);
        }
    } else {
        float As[16];
#pragma unroll
        for (int s = 0; s < 16; s++) As[s] = -__expf(alog[(i * 256 + d) * 16 + s]);
        for (int t = t0; t < t0 + LC; t++) {
            const float4* r = (const float4*)&pBC[t * 40];
            float4 a0 = r[0], a1 = r[1];
            float pre = dbias;
            pre = fmaf(a0.x, dw0.x, pre); pre = fmaf(a0.y, dw0.y, pre);
            pre = fmaf(a0.z, dw0.z, pre); pre = fmaf(a0.w, dw0.w, pre);
            pre = fmaf(a1.x, dw1.x, pre); pre = fmaf(a1.y, dw1.y, pre);
            pre = fmaf(a1.z, dw1.z, pre); pre = fmaf(a1.w, dw1.w, pre);
            float dv = softplusf(pre);
            float du = dv * pU[t * 256];
            dsum += dv;
            const float* Bp = &pBC[t * 40 + 8];
#pragma unroll
            for (int s = 0; s < 16; s++) {
                float a = __expf(dv * As[s]);
                h[s] = fmaf(a, h[s], du * Bp[s]);
            }
        }
    }
    int base = ((ib * NCHUNK + c) * 256 + d) * 16;
#pragma unroll
    for (int s = 0; s < 16; s++) {
        float Ascale = pw ? (A0 * (float)(s + 1))
                          : (-__expf(alog[(i * 256 + d) * 16 + s]));
        g_CP[base + s] = __expf(Ascale * dsum);
        g_CH[base + s] = h[s];
    }
}

// ---------------------------------------------------------------------------
// K5b: prefix over chunks
// ---------------------------------------------------------------------------
__global__ void k_scan2() {
    int g = blockIdx.x * 256 + threadIdx.x;
    int ib = g >> 12;
    int rem = g & 4095;
    float hi = 0.0f;
    for (int c = 0; c < NCHUNK; c++) {
        int idx = ib * (NCHUNK * 4096) + c * 4096 + rem;
        g_HI[idx] = hi;
        hi = fmaf(g_CP[idx], hi, g_CH[idx]);
    }
}

// ---------------------------------------------------------------------------
// K5c: chunk recompute with true h_init; y -> YT token-major.
// z in g_XZ is already silu'd by gemm_in epilogue.
// ---------------------------------------------------------------------------
__global__ void k_scan3(const float* __restrict__ alog, const float* __restrict__ Dv,
                        const float* __restrict__ dtw, const float* __restrict__ dtb) {
    int c = blockIdx.x, ib = blockIdx.y;
    int i = ib >> 2;
    int T = scanT(i);
    int LC = T / NCHUNK;
    int d = threadIdx.x;
    int SB = c_TB[ib];
    bool pw = (g_powBad == 0);
    float A0 = -__expf(alog[(i * 256 + d) * 16]);
    float Dreg = Dv[i * 256 + d];
    float4 dw0 = *(const float4*)&dtw[(i * 256 + d) * 8];
    float4 dw1 = *(const float4*)&dtw[(i * 256 + d) * 8 + 4];
    float dbias = dtb[i * 256 + d];
    const float* pU = &g_XS[SB * 256 + d];
    const float* pZ = &g_XZ[SB * 512 + 256 + d];
    const float* pBC = &g_XDBL[SB * 40];
    float* pY = &g_YT[SB * 256 + d];
    float h[16];
    {
        int base = ((ib * NCHUNK + c) * 256 + d) * 16;
#pragma unroll
        for (int s = 0; s < 16; s++) h[s] = g_HI[base + s];
    }
    int t0 = c * LC;
    if (pw) {
#pragma unroll 2
        for (int t = t0; t < t0 + LC; t++) {
            const float4* r = (const float4*)&pBC[t * 40];
            float4 a0 = r[0], a1 = r[1];
            float pre = dbias;
            pre = fmaf(a0.x, dw0.x, pre); pre = fmaf(a0.y, dw0.y, pre);
            pre = fmaf(a0.z, dw0.z, pre); pre = fmaf(a0.w, dw0.w, pre);
            pre = fmaf(a1.x, dw1.x, pre); pre = fmaf(a1.y, dw1.y, pre);
            pre = fmaf(a1.z, dw1.z, pre); pre = fmaf(a1.w, dw1.w, pre);
            float dv = softplusf(pre);
            float u = pU[t * 256];
            float du = dv * u;
            float q = __expf(dv * A0);
            float4 B0 = r[2], B1 = r[3], B2 = r[4], B3 = r[5];
            float4 C0 = r[6], C1 = r[7], C2 = r[8], C3 = r[9];
            float ys = 0.0f;
            float ap = q;
            h[0]  = fmaf(ap, h[0],  du * B0.x); ys = fmaf(h[0],  C0.x, ys); ap *= q;
            h[1]  = fmaf(ap, h[1],  du * B0.y); ys = fmaf(h[1],  C0.y, ys); ap *= q;
            h[2]  = fmaf(ap, h[2],  du * B0.z); ys = fmaf(h[2],  C0.z, ys); ap *= q;
            h[3]  = fmaf(ap, h[3],  du * B0.w); ys = fmaf(h[3],  C0.w, ys); ap *= q;
            h[4]  = fmaf(ap, h[4],  du * B1.x); ys = fmaf(h[4],  C1.x, ys); ap *= q;
            h[5]  = fmaf(ap, h[5],  du * B1.y); ys = fmaf(h[5],  C1.y, ys); ap *= q;
            h[6]  = fmaf(ap, h[6],  du * B1.z); ys = fmaf(h[6],  C1.z, ys); ap *= q;
            h[7]  = fmaf(ap, h[7],  du * B1.w); ys = fmaf(h[7],  C1.w, ys); ap *= q;
            h[8]  = fmaf(ap, h[8],  du * B2.x); ys = fmaf(h[8],  C2.x, ys); ap *= q;
            h[9]  = fmaf(ap, h[9],  du * B2.y); ys = fmaf(h[9],  C2.y, ys); ap *= q;
            h[10] = fmaf(ap, h[10], du * B2.z); ys = fmaf(h[10], C2.z, ys); ap *= q;
            h[11] = fmaf(ap, h[11], du * B2.w); ys = fmaf(h[11], C2.w, ys); ap *= q;
            h[12] = fmaf(ap, h[12], du * B3.x); ys = fmaf(h[12], C3.x, ys); ap *= q;
            h[13] = fmaf(ap, h[13], du * B3.y); ys = fmaf(h[13], C3.y, ys); ap *= q;
            h[14] = fmaf(ap, h[14], du * B3.z); ys = fmaf(h[14], C3.z, ys); ap *= q;
            h[15] = fmaf(ap, h[15], du * B3.w); ys = fmaf(h[15], C3.w, ys);
            float z = pZ[t * 512];
            pY[t * 256] = fmaf(u, Dreg, ys) * z;
        }
    } else {
        float As[16];
#pragma unroll
        for (int s = 0; s < 16; s++) As[s] = -__expf(alog[(i * 256 + d) * 16 + s]);
        for (int t = t0; t < t0 + LC; t++) {
            const float4* r = (const float4*)&pBC[t * 40];
            float4 a0 = r[0], a1 = r[1];
            float pre = dbias;
            pre = fmaf(a0.x, dw0.x, pre); pre = fmaf(a0.y, dw0.y, pre);
            pre = fmaf(a0.z, dw0.z, pre); pre = fmaf(a0.w, dw0.w, pre);
            pre = fmaf(a1.x, dw1.x, pre); pre = fmaf(a1.y, dw1.y, pre);
            pre = fmaf(a1.z, dw1.z, pre); pre = fmaf(a1.w, dw1.w, pre);
            float dv = softplusf(pre);
            float u = pU[t * 256];
            float du = dv * u;
            const float* Bp = &pBC[t * 40 + 8];
            float ys = 0.0f;
#pragma unroll
            for (int s = 0; s < 16; s++) {
                float a = __expf(dv * As[s]);
                h[s] = fmaf(a, h[s], du * Bp[s]);
                ys = fmaf(h[s], Bp[16 + s], ys);
            }
            float z = pZ[t * 512];
            pY[t * 256] = fmaf(u, Dreg, ys) * z;
        }
    }
}

// ---------------------------------------------------------------------------
// K6: out_proj tf32 GEMM.  tile 128x64, K=256, nt in {0,1}.
// ---------------------------------------------------------------------------
__global__ void k_gemm_out() {
    __shared__ __align__(16) float As[128][36];
    __shared__ __align__(16) float Bs[32][72];
    int nt = blockIdx.x;
    int tt = blockIdx.y;
    int ib = blockIdx.z;
    int i = ib >> 2;
    int T = scanT(i);
    if (tt * 128 >= T) return;
    int t0 = tt * 128;
    int SB = c_TB[ib];
    int tid = threadIdx.x;
    int warp = tid >> 5, lane = tid & 31;
    int wm = warp & 3, wn = warp >> 2;
    int lg = lane >> 2, lt = lane & 3;
    float c[2][4][4] = {};
    for (int kc = 0; kc < 8; kc++) {
        for (int p = 0; p < 4; p++) {
            int q = p * 256 + tid;
            int kk4 = q & 7, m = q >> 3;
            float4 v = *(const float4*)&g_YT[(SB + t0 + m) * 256 + kc * 32 + kk4 * 4];
            float4 w = make_float4(tf(v.x), tf(v.y), tf(v.z), tf(v.w));
            *(float4*)&As[m][kk4 * 4] = w;
        }
        for (int p = 0; p < 2; p++) {
            int q = p * 256 + tid;
            int n4 = q & 15, kk = q >> 4;
            float4 v = *(const float4*)&g_WTout[(i * 256 + kc * 32 + kk) * 128 + nt * 64 + n4 * 4];
            float4 w = make_float4(tf(v.x), tf(v.y), tf(v.z), tf(v.w));
            *(float4*)&Bs[kk][n4 * 4] = w;
        }
        __syncthreads();
#pragma unroll
        for (int k8 = 0; k8 < 4; k8++) {
            int kq = k8 * 8 + lt;
            uint32_t a[2][4];
#pragma unroll
            for (int mt = 0; mt < 2; mt++) {
                int mr = wm * 32 + mt * 16 + lg;
                a[mt][0] = fau(As[mr][kq]);     a[mt][1] = fau(As[mr + 8][kq]);
                a[mt][2] = fau(As[mr][kq + 4]); a[mt][3] = fau(As[mr + 8][kq + 4]);
            }
            uint32_t bb[4][2];
#pragma unroll
            for (int n4 = 0; n4 < 4; n4++) {
                int nb = wn * 32 + n4 * 8 + lg;
                bb[n4][0] = fau(Bs[kq][nb]);
                bb[n4][1] = fau(Bs[kq + 4][nb]);
            }
#pragma unroll
            for (int mt = 0; mt < 2; mt++)
#pragma unroll
                for (int n4 = 0; n4 < 4; n4++)
                    MMA_TF32(c[mt][n4], a[mt], bb[n4]);
        }
        __syncthreads();
    }
#pragma unroll
    for (int mt = 0; mt < 2; mt++)
#pragma unroll
        for (int n4 = 0; n4 < 4; n4++) {
            int row = t0 + wm * 32 + mt * 16 + lg;
            int col = nt * 64 + wn * 32 + n4 * 8 + 2 * lt;
            *(float2*)&g_OUT[(SB + row) * 128 + col]     = make_float2(c[mt][n4][0], c[mt][n4][1]);
            *(float2*)&g_OUT[(SB + row + 8) * 128 + col] = make_float2(c[mt][n4][2], c[mt][n4][3]);
        }
}

// interp of backward-scan output
__device__ __forceinline__ float interp_flip(int i, int b, int l, int c) {
    float pos = 0.5f * (float)(8191 - l) - 0.25f;
    pos = fminf(fmaxf(pos, 0.0f), 4095.0f);
    int lo = (int)floorf(pos);
    int hi = min(lo + 1, 4095);
    float w = pos - (float)lo;
    const float* ob = &g_OUT[c_TB[i * 4 + b] * 128 + c];
    return ob[lo * 128] * (1.0f - w) + ob[hi * 128] * w;
}

// ---------------------------------------------------------------------------
// K7: merge 4 scan outputs -> a,b maps [2][B][C][64][64]
// ---------------------------------------------------------------------------
__global__ void k_merge() {
    __shared__ float S[64][129];
    int irow = blockIdx.x;
    int b = blockIdx.y;
    int tid = threadIdx.x;
    for (int half = 0; half < 2; half++) {
        for (int p = 0; p < 32; p++) {
            int idx = p * 256 + tid;
            int c = idx & 127, j = idx >> 7;
            int l  = irow * 128 + j + (half ? 64 : 0);
            int l2 = j * 128 + irow + (half ? 64 : 0);
            float v = g_OUT[(c_TB[b] + l) * 128 + c];
            v += interp_flip(1, b, l, c);
            v += g_OUT[(c_TB[8 + b] + l2) * 128 + c];
            v += interp_flip(3, b, l2, c);
            S[j][c] = v;
        }
        __syncthreads();
        for (int p = 0; p < 32; p++) {
            int idx = p * 256 + tid;
            int j = idx & 63, c = idx >> 6;
            g_AB[((half * 4 + b) * 128 + c) * 4096 + irow * 64 + j] = S[j][c];
        }
        __syncthreads();
    }
}

// ---------------------------------------------------------------------------
// K8: bilinear 64->128 upsample + residuals
// ---------------------------------------------------------------------------
__global__ void k_final(const float* __restrict__ fa, const float* __restrict__ fb,
                        float* __restrict__ out) {
    int idx = blockIdx.x * 256 + threadIdx.x;
    int w = idx & 127, hh = (idx >> 7) & 127, c = (idx >> 14) & 127, b = idx >> 21;
    float ph = fminf(fmaxf(0.5f * hh - 0.25f, 0.0f), 63.0f);
    int h0 = (int)floorf(ph); int h1 = min(h0 + 1, 63); float wh = ph - (float)h0;
    float pw = fminf(fmaxf(0.5f * w - 0.25f, 0.0f), 63.0f);
    int w0 = (int)floorf(pw); int w1 = min(w0 + 1, 63); float ww = pw - (float)w0;
    const float* Aa = &g_AB[((0 * 4 + b) * 128 + c) * 4096];
    const float* Bb = &g_AB[((1 * 4 + b) * 128 + c) * 4096];
    float av = (Aa[h0 * 64 + w0] * (1.0f - ww) + Aa[h0 * 64 + w1] * ww) * (1.0f - wh)
             + (Aa[h1 * 64 + w0] * (1.0f - ww) + Aa[h1 * 64 + w1] * ww) * wh;
    float bv = (Bb[h0 * 64 + w0] * (1.0f - ww) + Bb[h0 * 64 + w1] * ww) * (1.0f - wh)
             + (Bb[h1 * 64 + w0] * (1.0f - ww) + Bb[h1 * 64 + w1] * ww) * wh;
    out[idx] = av + bv + fa[idx] + fb[idx];
}

// ---------------------------------------------------------------------------
extern "C" void kernel_launch(void* const* d_in, const int* in_sizes, int n_in,
                              void* d_out, int out_size) {
    (void)in_sizes; (void)n_in; (void)out_size;
    const float* fa   = (const float*)d_in[0];
    const float* fb   = (const float*)d_in[1];
    const float* inw  = (const float*)d_in[2];
    const float* cw   = (const float*)d_in[3];
    const float* cb   = (const float*)d_in[4];
    const float* xpw  = (const float*)d_in[5];
    const float* dtw  = (const float*)d_in[6];
    const float* dtb  = (const float*)d_in[7];
    const float* alog = (const float*)d_in[8];
    const float* Dv   = (const float*)d_in[9];
    const float* outw = (const float*)d_in[10];
    float* out = (float*)d_out;

    k_gather<<<dim3(2, 64, 4), 256>>>(fa, fb);
    k_prep_w<<<1024, 256>>>(inw, xpw, outw);
    k_prep_chk<<<64, 256>>>(alog);
    k_gemm_in<<<dim3(8, 64, 16), 256>>>();
    k_conv<<<dim3(128, 16), 256>>>(cw, cb);
    k_gemm_xp<<<dim3(1, 64, 16), 256>>>();
    k_scan1<<<dim3(NCHUNK, 16), 256>>>(alog, dtw, dtb);
    k_scan2<<<256, 256>>>();
    k_scan3<<<dim3(NCHUNK, 16), 256>>>(alog, Dv, dtw, dtb);
    k_gemm_out<<<dim3(2, 64, 16), 256>>>();
    k_merge<<<dim3(64, 4), 256>>>();
    k_final<<<32768, 256>>>(fa, fb, out);
}